// round 1
// baseline (speedup 1.0000x reference)
#include <cuda_runtime.h>
#include <cuda_bf16.h>
#include <math.h>

#define NN 20000
#define HH 512
#define EE 200000

// ---------------- scratch (static device globals; no allocation) ----------------
__device__ float g_bufA[NN * HH];
__device__ float g_bufB[NN * HH];
__device__ float g_bufC[NN * HH];
__device__ float g_bufD[NN * HH];
__device__ float g_bufF[NN * HH];
__device__ float g_bufG[NN * HH];
__device__ float g_hp[NN * HH];
__device__ float g_ssc[NN];
__device__ float g_tsc[NN];
__device__ float g_den[NN];
__device__ float g_ew[EE];

// ---------------- GEMM: C[M,512] = A[M,K] @ W[K,512] + bias (op1: tanh) ----------
#define BM 128
#define BN 128
#define BK 8

__global__ __launch_bounds__(256) void sgemm_kernel(
    const float* __restrict__ A, const float* __restrict__ W,
    const float* __restrict__ bias, float* __restrict__ C,
    int M, int K, int op)
{
    const int NC = 512;
    __shared__ float As[BK][BM];
    __shared__ float Bs[BK][BN];

    int tid = threadIdx.x;
    int rowBase = blockIdx.y * BM;
    int colBase = blockIdx.x * BN;
    int ty = tid >> 4;        // 0..15
    int tx = tid & 15;        // 0..15

    float acc[8][8];
#pragma unroll
    for (int i = 0; i < 8; i++)
#pragma unroll
        for (int j = 0; j < 8; j++) acc[i][j] = 0.f;

    int aRow = tid >> 1;           // 0..127
    int aCol = (tid & 1) * 4;      // 0 or 4
    int bRow = tid >> 5;           // 0..7
    int bCol = (tid & 31) * 4;     // 0..124

    bool aValid = (rowBase + aRow) < M;
    const float* Aptr = A + (size_t)(rowBase + aRow) * K + aCol;
    const float* Wptr = W + (size_t)bRow * NC + colBase + bCol;

    for (int k0 = 0; k0 < K; k0 += BK) {
        float4 av = aValid ? *(const float4*)(Aptr + k0) : make_float4(0.f, 0.f, 0.f, 0.f);
        float4 bv = *(const float4*)(Wptr + (size_t)k0 * NC);
        As[aCol + 0][aRow] = av.x;
        As[aCol + 1][aRow] = av.y;
        As[aCol + 2][aRow] = av.z;
        As[aCol + 3][aRow] = av.w;
        *(float4*)&Bs[bRow][bCol] = bv;
        __syncthreads();
#pragma unroll
        for (int k = 0; k < BK; k++) {
            float a[8], b[8];
            *(float4*)&a[0] = *(const float4*)&As[k][ty * 8];
            *(float4*)&a[4] = *(const float4*)&As[k][ty * 8 + 4];
            *(float4*)&b[0] = *(const float4*)&Bs[k][tx * 8];
            *(float4*)&b[4] = *(const float4*)&Bs[k][tx * 8 + 4];
#pragma unroll
            for (int i = 0; i < 8; i++)
#pragma unroll
                for (int j = 0; j < 8; j++) acc[i][j] += a[i] * b[j];
        }
        __syncthreads();
    }

#pragma unroll
    for (int i = 0; i < 8; i++) {
        int row = rowBase + ty * 8 + i;
        if (row >= M) continue;
        float* crow = C + (size_t)row * NC + colBase + tx * 8;
#pragma unroll
        for (int j = 0; j < 8; j += 4) {
            float4 v;
            v.x = acc[i][j + 0] + __ldg(&bias[colBase + tx * 8 + j + 0]);
            v.y = acc[i][j + 1] + __ldg(&bias[colBase + tx * 8 + j + 1]);
            v.z = acc[i][j + 2] + __ldg(&bias[colBase + tx * 8 + j + 2]);
            v.w = acc[i][j + 3] + __ldg(&bias[colBase + tx * 8 + j + 3]);
            if (op == 1) {
                v.x = tanhf(v.x); v.y = tanhf(v.y); v.z = tanhf(v.z); v.w = tanhf(v.w);
            }
            *(float4*)(crow + j) = v;
        }
    }
}

// ---------------- per-row dot: out[r] = X[r,:] . v  (mode1: sigmoid(+bias)) -----
__global__ void rowdot_kernel(const float* __restrict__ X, const float* __restrict__ v,
                              const float* __restrict__ bptr, float* __restrict__ out,
                              int n, int mode)
{
    int w = (blockIdx.x * blockDim.x + threadIdx.x) >> 5;
    int lane = threadIdx.x & 31;
    if (w >= n) return;
    const float4* xr = ((const float4*)X) + (size_t)w * 128;
    const float4* vr = (const float4*)v;
    float s = 0.f;
#pragma unroll
    for (int i = 0; i < 4; i++) {
        float4 a = xr[lane + 32 * i];
        float4 b = __ldg(&vr[lane + 32 * i]);
        s += a.x * b.x + a.y * b.y + a.z * b.z + a.w * b.w;
    }
#pragma unroll
    for (int o = 16; o > 0; o >>= 1) s += __shfl_xor_sync(0xffffffffu, s, o);
    if (lane == 0) {
        if (mode == 1) out[w] = 1.f / (1.f + expf(-(s + bptr[0])));
        else out[w] = s;
    }
}

// ---------------- edge pass 1: ew = exp(tanh(ssc[src]+tsc[tgt]+ab)), den[src]+= --
__global__ void edge_p1_kernel(const int* __restrict__ src, const int* __restrict__ tgt,
                               const float* __restrict__ ssc, const float* __restrict__ tsc,
                               const float* __restrict__ abptr, int abidx,
                               float* __restrict__ ew, float* __restrict__ den, int E)
{
    int i = blockIdx.x * blockDim.x + threadIdx.x;
    if (i >= E) return;
    float e = tanhf(ssc[src[i]] + tsc[tgt[i]] + abptr[abidx]);
    float x = expf(e);
    ew[i] = x;
    atomicAdd(&den[src[i]], x);
}

// ---------------- scatter: hp[src] += alpha * t[tgt]  (warp per edge) -----------
__global__ void scatter_kernel(const int* __restrict__ src, const int* __restrict__ tgt,
                               const float* __restrict__ ew, const float* __restrict__ den,
                               const float* __restrict__ t, float* __restrict__ hp, int E)
{
    int e = (blockIdx.x * blockDim.x + threadIdx.x) >> 5;
    int lane = threadIdx.x & 31;
    if (e >= E) return;
    int s = src[e], g = tgt[e];
    float alpha = ew[e] / den[s];
    const float4* tr = ((const float4*)t) + (size_t)g * 128;
    float* hr = hp + (size_t)s * 512;
#pragma unroll
    for (int i = 0; i < 4; i++) {
        float4 v = tr[lane + 32 * i];
        int base = (lane + 32 * i) * 4;
        atomicAdd(hr + base + 0, v.x * alpha);
        atomicAdd(hr + base + 1, v.y * alpha);
        atomicAdd(hr + base + 2, v.z * alpha);
        atomicAdd(hr + base + 3, v.w * alpha);
    }
}

// ---------------- combine: out = (h + hp + gbias) * 0.5 ------------------------
__global__ void combine_kernel(const float* __restrict__ h, const float* __restrict__ hp,
                               const float* __restrict__ gb, float* __restrict__ out, int total4)
{
    int i = blockIdx.x * blockDim.x + threadIdx.x;
    if (i >= total4) return;
    float4 a = ((const float4*)h)[i];
    float4 c = ((const float4*)hp)[i];
    float4 g = __ldg(&((const float4*)gb)[i & 127]);
    float4 r;
    r.x = (a.x + c.x + g.x) * 0.5f;
    r.y = (a.y + c.y + g.y) * 0.5f;
    r.z = (a.z + c.z + g.z) * 0.5f;
    r.w = (a.w + c.w + g.w) * 0.5f;
    ((float4*)out)[i] = r;
}

// ---------------- layernorm (in place). mode1: v = tanh(x + x2) first ------------
__global__ void ln_kernel(float* __restrict__ x, const float* __restrict__ x2,
                          const float* __restrict__ g, const float* __restrict__ b, int mode)
{
    int row = blockIdx.x;
    int tid = threadIdx.x;     // 128 threads, 4 floats each
    float4* xr = ((float4*)x) + (size_t)row * 128;
    float4 v = xr[tid];
    if (mode == 1) {
        float4 w = ((const float4*)x2)[(size_t)row * 128 + tid];
        v.x = tanhf(v.x + w.x); v.y = tanhf(v.y + w.y);
        v.z = tanhf(v.z + w.z); v.w = tanhf(v.w + w.w);
    }
    float sum = v.x + v.y + v.z + v.w;
    float sq  = v.x * v.x + v.y * v.y + v.z * v.z + v.w * v.w;
#pragma unroll
    for (int o = 16; o > 0; o >>= 1) {
        sum += __shfl_xor_sync(0xffffffffu, sum, o);
        sq  += __shfl_xor_sync(0xffffffffu, sq, o);
    }
    __shared__ float ssum[4], ssq[4], sstat[2];
    int wid = tid >> 5, lane = tid & 31;
    if (lane == 0) { ssum[wid] = sum; ssq[wid] = sq; }
    __syncthreads();
    if (tid == 0) {
        float ts = ssum[0] + ssum[1] + ssum[2] + ssum[3];
        float tq = ssq[0] + ssq[1] + ssq[2] + ssq[3];
        float mu = ts * (1.f / 512.f);
        float var = tq * (1.f / 512.f) - mu * mu;
        sstat[0] = mu;
        sstat[1] = rsqrtf(var + 1e-5f);
    }
    __syncthreads();
    float mu = sstat[0], rstd = sstat[1];
    float4 gg = __ldg(&((const float4*)g)[tid]);
    float4 bb = __ldg(&((const float4*)b)[tid]);
    v.x = (v.x - mu) * rstd * gg.x + bb.x;
    v.y = (v.y - mu) * rstd * gg.y + bb.y;
    v.z = (v.z - mu) * rstd * gg.z + bb.z;
    v.w = (v.w - mu) * rstd * gg.w + bb.w;
    xr[tid] = v;
}

// ---------------- zero (float4) ----------------
__global__ void zero_kernel(float* __restrict__ p, int n4)
{
    int i = blockIdx.x * blockDim.x + threadIdx.x;
    if (i < n4) ((float4*)p)[i] = make_float4(0.f, 0.f, 0.f, 0.f);
}

// =====================================================================================
extern "C" void kernel_launch(void* const* d_in, const int* in_sizes, int n_in,
                              void* d_out, int out_size)
{
    const int N = NN, H = HH, E = EE;

    // inputs in reference signature order
    const float* fu0 = (const float*)d_in[0];
    // d_in[1] feat_item_h0 (unused)
    // d_in[2] feat_user_h1 (unused)
    const float* fi1 = (const float*)d_in[3];
    const float* fu2 = (const float*)d_in[4];
    // d_in[5] feat_item_h2 (unused)
    const int* eUI0 = (const int*)d_in[6];
    // d_in[7] edges_IU_h0 (unused)
    // d_in[8] edges_UI_h1 (unused — relation-0 at hop1 is dead code)
    const int* eIU1 = (const int*)d_in[9];
    const float* Wu   = (const float*)d_in[10];
    const float* bu   = (const float*)d_in[11];
    const float* Wi   = (const float*)d_in[12];
    const float* bi   = (const float*)d_in[13];
    const float* gatW = (const float*)d_in[14];
    const float* gatb = (const float*)d_in[15];
    const float* aw   = (const float*)d_in[16];
    const float* ab   = (const float*)d_in[17];
    const float* gbias= (const float*)d_in[18];
    const float* prepW= (const float*)d_in[19];
    const float* prepb= (const float*)d_in[20];
    const float* dnnW = (const float*)d_in[21];
    const float* dnnb = (const float*)d_in[22];
    const float* lng  = (const float*)d_in[23];
    const float* lnb  = (const float*)d_in[24];
    const float* rlng = (const float*)d_in[25];
    const float* rlnb = (const float*)d_in[26];
    const float* clsW = (const float*)d_in[27];
    const float* clsb = (const float*)d_in[28];

    float *bufA, *bufB, *bufC, *bufD, *bufF, *bufG, *hp, *ssc, *tsc, *den, *ew;
    cudaGetSymbolAddress((void**)&bufA, g_bufA);
    cudaGetSymbolAddress((void**)&bufB, g_bufB);
    cudaGetSymbolAddress((void**)&bufC, g_bufC);
    cudaGetSymbolAddress((void**)&bufD, g_bufD);
    cudaGetSymbolAddress((void**)&bufF, g_bufF);
    cudaGetSymbolAddress((void**)&bufG, g_bufG);
    cudaGetSymbolAddress((void**)&hp,   g_hp);
    cudaGetSymbolAddress((void**)&ssc,  g_ssc);
    cudaGetSymbolAddress((void**)&tsc,  g_tsc);
    cudaGetSymbolAddress((void**)&den,  g_den);
    cudaGetSymbolAddress((void**)&ew,   g_ew);

    dim3 gemmGrid(4, (N + BM - 1) / BM);
    const int rowdotBlocks = (N * 32 + 255) / 256;
    const int edgeBlocks = (E + 255) / 256;
    const int scatBlocks = (E * 32 + 255) / 256;
    const int nh4 = N * (H / 4);
    const int zeroHPblocks = (nh4 + 255) / 256;
    const int zeroDenBlocks = ((N / 4) + 255) / 256;

    // --- deep transforms ---
    sgemm_kernel<<<gemmGrid, 256>>>(fu2, Wu, bu, bufA, N, 512, 0);    // su_h2
    sgemm_kernel<<<gemmGrid, 256>>>(fi1, Wi, bi, bufB, N, 256, 0);    // hi_h1

    // --- GAT relation 1 @ hop 1: head=hi_h1, tail=su_h2, edges_IU_h1 ---
    const float* fW1 = gatW + H * H;
    const float* fb1 = gatb + H;
    sgemm_kernel<<<gemmGrid, 256>>>(bufB, fW1, fb1, bufC, N, 512, 0); // s1
    sgemm_kernel<<<gemmGrid, 256>>>(bufA, fW1, fb1, bufD, N, 512, 0); // t1
    rowdot_kernel<<<rowdotBlocks, 256>>>(bufC, aw + 2 * H, nullptr, ssc, N, 0);
    rowdot_kernel<<<rowdotBlocks, 256>>>(bufD, aw + 2 * H + H, nullptr, tsc, N, 0);
    zero_kernel<<<zeroHPblocks, 256>>>(hp, nh4);
    zero_kernel<<<zeroDenBlocks, 256>>>(den, N / 4);
    edge_p1_kernel<<<edgeBlocks, 256>>>(eIU1, eIU1 + E, ssc, tsc, ab, 1, ew, den, E);
    scatter_kernel<<<scatBlocks, 256>>>(eIU1, eIU1 + E, ew, den, bufD, hp, E);
    combine_kernel<<<(nh4 + 255) / 256, 256>>>(bufB, hp, gbias + H, bufF, nh4);  // si_new

    // --- hop 0 ---
    sgemm_kernel<<<gemmGrid, 256>>>(fu0, Wu, bu, bufG, N, 512, 0);    // hu_h0
    sgemm_kernel<<<gemmGrid, 256>>>(bufG, gatW, gatb, bufC, N, 512, 0); // s0
    sgemm_kernel<<<gemmGrid, 256>>>(bufF, gatW, gatb, bufD, N, 512, 0); // t0
    rowdot_kernel<<<rowdotBlocks, 256>>>(bufC, aw, nullptr, ssc, N, 0);
    rowdot_kernel<<<rowdotBlocks, 256>>>(bufD, aw + H, nullptr, tsc, N, 0);
    zero_kernel<<<zeroHPblocks, 256>>>(hp, nh4);
    zero_kernel<<<zeroDenBlocks, 256>>>(den, N / 4);
    edge_p1_kernel<<<edgeBlocks, 256>>>(eUI0, eUI0 + E, ssc, tsc, ab, 0, ew, den, E);
    scatter_kernel<<<scatBlocks, 256>>>(eUI0, eUI0 + E, ew, den, bufD, hp, E);
    combine_kernel<<<(nh4 + 255) / 256, 256>>>(bufG, hp, gbias, bufA, nh4);      // su_final

    // --- Res_DNN head ---
    sgemm_kernel<<<gemmGrid, 256>>>(bufA, prepW, prepb, bufB, N, 512, 0);        // x
    for (int r = 0; r < 2; r++) {
        sgemm_kernel<<<gemmGrid, 256>>>(bufB, dnnW + (size_t)(r * 2 + 0) * H * H,
                                        dnnb + (r * 2 + 0) * H, bufC, N, 512, 1);
        ln_kernel<<<N, 128>>>(bufC, nullptr, lng + (r * 2 + 0) * H, lnb + (r * 2 + 0) * H, 0);
        sgemm_kernel<<<gemmGrid, 256>>>(bufC, dnnW + (size_t)(r * 2 + 1) * H * H,
                                        dnnb + (r * 2 + 1) * H, bufD, N, 512, 1);
        ln_kernel<<<N, 128>>>(bufD, nullptr, lng + (r * 2 + 1) * H, lnb + (r * 2 + 1) * H, 0);
        ln_kernel<<<N, 128>>>(bufB, bufD, rlng + r * H, rlnb + r * H, 1);        // x = LN(tanh(sc+x))
    }

    // --- classifier + sigmoid ---
    rowdot_kernel<<<rowdotBlocks, 256>>>(bufB, clsW, clsb, (float*)d_out, N, 1);
}

// round 3
// speedup vs baseline: 2.2185x; 2.2185x over previous
#include <cuda_runtime.h>
#include <cuda_bf16.h>
#include <math.h>
#include <stdint.h>

#define NN 20000
#define HH 512
#define EE 200000

// ---------------- scratch (static device globals; no allocation) ----------------
__device__ float g_bufA[NN * HH];
__device__ float g_bufB[NN * HH];
__device__ float g_bufC[NN * HH];
__device__ float g_bufD[NN * HH];
__device__ float g_bufF[NN * HH];
__device__ float g_bufG[NN * HH];
__device__ float g_hp[NN * HH];
__device__ float g_ssc[NN];
__device__ float g_tsc[NN];
__device__ float g_den[NN];
__device__ float g_ew[EE];
__device__ __nv_bfloat16 g_ah[NN * HH];     // A split hi  [M,K]
__device__ __nv_bfloat16 g_al[NN * HH];     // A split lo
__device__ __nv_bfloat16 g_bth[HH * HH];    // B^T split hi [512,K]
__device__ __nv_bfloat16 g_btl[HH * HH];    // B^T split lo

// ======================= portable tensor-core GEMM (mma.sync bf16) =======================
// C[M,512] = A[M,K] @ W[K,512] + bias, computed as Ah·Bh + Ah·Bl + Al·Bh with f32 accum.
// Block tile 128x128, BK=32, 8 warps (warp tile 64x32), cp.async double buffer.

#define BM 128
#define BN 128
#define BK 32
#define PAD 40                       // padded K-stride in halves (80B = 20 banks)
#define MAT_HALVES (BM * PAD)        // 5120 halves per matrix tile
#define STAGE_BYTES (4 * MAT_HALVES * 2)   // Ah|Al|Bh|Bl = 40960 B
#define GEMM_SMEM (2 * STAGE_BYTES)        // 81920 B

__device__ __forceinline__ void cp16(uint32_t saddr, const void* gptr) {
    asm volatile("cp.async.cg.shared.global [%0], [%1], 16;" :: "r"(saddr), "l"(gptr));
}
__device__ __forceinline__ void cp_commit() { asm volatile("cp.async.commit_group;"); }
template <int N> __device__ __forceinline__ void cp_wait() {
    asm volatile("cp.async.wait_group %0;" :: "n"(N));
}

__device__ __forceinline__ void mma16816(float* c, const uint32_t* a, const uint32_t* b) {
    asm volatile(
        "mma.sync.aligned.m16n8k16.row.col.f32.bf16.bf16.f32 "
        "{%0,%1,%2,%3}, {%4,%5,%6,%7}, {%8,%9}, {%0,%1,%2,%3};"
        : "+f"(c[0]), "+f"(c[1]), "+f"(c[2]), "+f"(c[3])
        : "r"(a[0]), "r"(a[1]), "r"(a[2]), "r"(a[3]), "r"(b[0]), "r"(b[1]));
}

__global__ __launch_bounds__(256, 1)
void tc_gemm(const __nv_bfloat16* __restrict__ Ah, const __nv_bfloat16* __restrict__ Al,
             const __nv_bfloat16* __restrict__ Bh, const __nv_bfloat16* __restrict__ Bl,
             const float* __restrict__ bias, float* __restrict__ C,
             int M, int K, int op)
{
    extern __shared__ __nv_bfloat16 sm[];
    const int tid = threadIdx.x;
    const int wid = tid >> 5;
    const int lane = tid & 31;
    const int rowBase = blockIdx.y * BM;
    const int colBase = blockIdx.x * BN;
    const int nChunks = K >> 5;

    const int m_base = (wid & 1) * 64;       // 2 warp-rows
    const int n_base = (wid >> 1) * 32;      // 4 warp-cols

    const uint32_t smemBase = (uint32_t)__cvta_generic_to_shared(sm);

    float acc[4][4][4];
#pragma unroll
    for (int mi = 0; mi < 4; mi++)
#pragma unroll
        for (int nj = 0; nj < 4; nj++)
#pragma unroll
            for (int r = 0; r < 4; r++) acc[mi][nj][r] = 0.f;

    // ---- stage loader: 512 16B-chunks per matrix, 4 matrices ----
    auto loadStage = [&](int s, int k0) {
        uint32_t st = smemBase + s * STAGE_BYTES;
#pragma unroll
        for (int i = 0; i < 2; i++) {
            int chunk = tid + i * 256;       // 0..511
            int r = chunk >> 2;
            int seg = chunk & 3;             // 8 halves each
            uint32_t dst = st + (uint32_t)(r * PAD + seg * 8) * 2;
            int grow = rowBase + r; if (grow > M - 1) grow = M - 1;
            size_t aoff = (size_t)grow * K + k0 + seg * 8;
            cp16(dst, Ah + aoff);
            cp16(dst + MAT_HALVES * 2, Al + aoff);
            int gn = colBase + r;
            size_t boff = (size_t)gn * K + k0 + seg * 8;
            cp16(dst + 2 * MAT_HALVES * 2, Bh + boff);
            cp16(dst + 3 * MAT_HALVES * 2, Bl + boff);
        }
    };

    loadStage(0, 0);
    cp_commit();

    for (int c = 0; c < nChunks; c++) {
        int s = c & 1;
        if (c + 1 < nChunks) { loadStage((c + 1) & 1, (c + 1) * BK); cp_commit(); cp_wait<1>(); }
        else cp_wait<0>();
        __syncthreads();

        const __nv_bfloat16* sA = sm + s * (4 * MAT_HALVES);
        const __nv_bfloat16* sAl = sA + MAT_HALVES;
        const __nv_bfloat16* sB = sA + 2 * MAT_HALVES;
        const __nv_bfloat16* sBl = sA + 3 * MAT_HALVES;

#pragma unroll
        for (int kk = 0; kk < BK; kk += 16) {
            uint32_t ah[4][4], al[4][4], bh[4][2], bl[4][2];
            int acol = kk + (lane & 3) * 2;
#pragma unroll
            for (int mi = 0; mi < 4; mi++) {
                int row = m_base + mi * 16 + (lane >> 2);
                ah[mi][0] = *(const uint32_t*)(sA + row * PAD + acol);
                ah[mi][1] = *(const uint32_t*)(sA + (row + 8) * PAD + acol);
                ah[mi][2] = *(const uint32_t*)(sA + row * PAD + acol + 8);
                ah[mi][3] = *(const uint32_t*)(sA + (row + 8) * PAD + acol + 8);
                al[mi][0] = *(const uint32_t*)(sAl + row * PAD + acol);
                al[mi][1] = *(const uint32_t*)(sAl + (row + 8) * PAD + acol);
                al[mi][2] = *(const uint32_t*)(sAl + row * PAD + acol + 8);
                al[mi][3] = *(const uint32_t*)(sAl + (row + 8) * PAD + acol + 8);
            }
#pragma unroll
            for (int nj = 0; nj < 4; nj++) {
                int n = n_base + nj * 8 + (lane >> 2);
                bh[nj][0] = *(const uint32_t*)(sB + n * PAD + acol);
                bh[nj][1] = *(const uint32_t*)(sB + n * PAD + acol + 8);
                bl[nj][0] = *(const uint32_t*)(sBl + n * PAD + acol);
                bl[nj][1] = *(const uint32_t*)(sBl + n * PAD + acol + 8);
            }
#pragma unroll
            for (int mi = 0; mi < 4; mi++)
#pragma unroll
                for (int nj = 0; nj < 4; nj++) {
                    mma16816(acc[mi][nj], ah[mi], bh[nj]);
                    mma16816(acc[mi][nj], ah[mi], bl[nj]);
                    mma16816(acc[mi][nj], al[mi], bh[nj]);
                }
        }
        __syncthreads();
    }

    // ---- epilogue: bias + optional tanh, 64-bit stores ----
#pragma unroll
    for (int mi = 0; mi < 4; mi++) {
        int row0 = rowBase + m_base + mi * 16 + (lane >> 2);
        int row1 = row0 + 8;
#pragma unroll
        for (int nj = 0; nj < 4; nj++) {
            int col = colBase + n_base + nj * 8 + (lane & 3) * 2;
            float b0 = __ldg(bias + col), b1 = __ldg(bias + col + 1);
            float2 v0 = make_float2(acc[mi][nj][0] + b0, acc[mi][nj][1] + b1);
            float2 v1 = make_float2(acc[mi][nj][2] + b0, acc[mi][nj][3] + b1);
            if (op == 1) {
                v0.x = tanhf(v0.x); v0.y = tanhf(v0.y);
                v1.x = tanhf(v1.x); v1.y = tanhf(v1.y);
            }
            if (row0 < M) *(float2*)(C + (size_t)row0 * 512 + col) = v0;
            if (row1 < M) *(float2*)(C + (size_t)row1 * 512 + col) = v1;
        }
    }
}

// ---------------- split fp32 -> bf16 hi/lo (elementwise, float4) ----------------
__global__ void split_kernel(const float* __restrict__ X, __nv_bfloat16* __restrict__ h,
                             __nv_bfloat16* __restrict__ l, int n4)
{
    int i = blockIdx.x * blockDim.x + threadIdx.x;
    if (i >= n4) return;
    float4 x = ((const float4*)X)[i];
    __nv_bfloat16 h0 = __float2bfloat16(x.x), h1 = __float2bfloat16(x.y);
    __nv_bfloat16 h2 = __float2bfloat16(x.z), h3 = __float2bfloat16(x.w);
    __nv_bfloat162* hp2 = (__nv_bfloat162*)h;
    __nv_bfloat162* lp2 = (__nv_bfloat162*)l;
    hp2[i * 2 + 0] = __nv_bfloat162(h0, h1);
    hp2[i * 2 + 1] = __nv_bfloat162(h2, h3);
    lp2[i * 2 + 0] = __nv_bfloat162(__float2bfloat16(x.x - __bfloat162float(h0)),
                                    __float2bfloat16(x.y - __bfloat162float(h1)));
    lp2[i * 2 + 1] = __nv_bfloat162(__float2bfloat16(x.z - __bfloat162float(h2)),
                                    __float2bfloat16(x.w - __bfloat162float(h3)));
}

// ------------- transpose + split weights: B[K,N] fp32 -> Bt hi/lo [N,K] bf16 -------------
__global__ void splitT_kernel(const float* __restrict__ B, __nv_bfloat16* __restrict__ th,
                              __nv_bfloat16* __restrict__ tl, int K, int Ncols)
{
    int idx = blockIdx.x * blockDim.x + threadIdx.x;
    if (idx >= K * Ncols) return;
    int n = idx / K, k = idx - n * K;
    float x = B[(size_t)k * Ncols + n];
    __nv_bfloat16 hi = __float2bfloat16(x);
    th[idx] = hi;
    tl[idx] = __float2bfloat16(x - __bfloat162float(hi));
}

// ---------------- per-row dot: out[r] = X[r,:] . v  (mode1: sigmoid(+bias)) -----
__global__ void rowdot_kernel(const float* __restrict__ X, const float* __restrict__ v,
                              const float* __restrict__ bptr, float* __restrict__ out,
                              int n, int mode)
{
    int w = (blockIdx.x * blockDim.x + threadIdx.x) >> 5;
    int lane = threadIdx.x & 31;
    if (w >= n) return;
    const float4* xr = ((const float4*)X) + (size_t)w * 128;
    const float4* vr = (const float4*)v;
    float s = 0.f;
#pragma unroll
    for (int i = 0; i < 4; i++) {
        float4 a = xr[lane + 32 * i];
        float4 b = __ldg(&vr[lane + 32 * i]);
        s += a.x * b.x + a.y * b.y + a.z * b.z + a.w * b.w;
    }
#pragma unroll
    for (int o = 16; o > 0; o >>= 1) s += __shfl_xor_sync(0xffffffffu, s, o);
    if (lane == 0) {
        if (mode == 1) out[w] = 1.f / (1.f + expf(-(s + bptr[0])));
        else out[w] = s;
    }
}

// ---------------- edge pass 1 ----------------
__global__ void edge_p1_kernel(const int* __restrict__ src, const int* __restrict__ tgt,
                               const float* __restrict__ ssc, const float* __restrict__ tsc,
                               const float* __restrict__ abptr, int abidx,
                               float* __restrict__ ew, float* __restrict__ den, int E)
{
    int i = blockIdx.x * blockDim.x + threadIdx.x;
    if (i >= E) return;
    float e = tanhf(ssc[src[i]] + tsc[tgt[i]] + abptr[abidx]);
    float x = expf(e);
    ew[i] = x;
    atomicAdd(&den[src[i]], x);
}

// ---------------- scatter (warp per edge, float4 vector atomics) -----------
__global__ void scatter_kernel(const int* __restrict__ src, const int* __restrict__ tgt,
                               const float* __restrict__ ew, const float* __restrict__ den,
                               const float* __restrict__ t, float* __restrict__ hp, int E)
{
    int e = (blockIdx.x * blockDim.x + threadIdx.x) >> 5;
    int lane = threadIdx.x & 31;
    if (e >= E) return;
    int s = src[e], g = tgt[e];
    float alpha = ew[e] / den[s];
    const float4* tr = ((const float4*)t) + (size_t)g * 128;
    float4* hr = ((float4*)(hp + (size_t)s * 512));
#pragma unroll
    for (int i = 0; i < 4; i++) {
        float4 v = tr[lane + 32 * i];
        float4 w = make_float4(v.x * alpha, v.y * alpha, v.z * alpha, v.w * alpha);
        atomicAdd(hr + lane + 32 * i, w);
    }
}

// ---------------- combine: out = (h + hp + gbias) * 0.5 ------------------------
__global__ void combine_kernel(const float* __restrict__ h, const float* __restrict__ hp,
                               const float* __restrict__ gb, float* __restrict__ out, int total4)
{
    int i = blockIdx.x * blockDim.x + threadIdx.x;
    if (i >= total4) return;
    float4 a = ((const float4*)h)[i];
    float4 c = ((const float4*)hp)[i];
    float4 g = __ldg(&((const float4*)gb)[i & 127]);
    float4 r;
    r.x = (a.x + c.x + g.x) * 0.5f;
    r.y = (a.y + c.y + g.y) * 0.5f;
    r.z = (a.z + c.z + g.z) * 0.5f;
    r.w = (a.w + c.w + g.w) * 0.5f;
    ((float4*)out)[i] = r;
}

// ---------------- layernorm (in place). mode1: v = tanh(x + x2) first ------------
__global__ void ln_kernel(float* __restrict__ x, const float* __restrict__ x2,
                          const float* __restrict__ g, const float* __restrict__ b, int mode)
{
    int row = blockIdx.x;
    int tid = threadIdx.x;
    float4* xr = ((float4*)x) + (size_t)row * 128;
    float4 v = xr[tid];
    if (mode == 1) {
        float4 w = ((const float4*)x2)[(size_t)row * 128 + tid];
        v.x = tanhf(v.x + w.x); v.y = tanhf(v.y + w.y);
        v.z = tanhf(v.z + w.z); v.w = tanhf(v.w + w.w);
    }
    float sum = v.x + v.y + v.z + v.w;
    float sq  = v.x * v.x + v.y * v.y + v.z * v.z + v.w * v.w;
#pragma unroll
    for (int o = 16; o > 0; o >>= 1) {
        sum += __shfl_xor_sync(0xffffffffu, sum, o);
        sq  += __shfl_xor_sync(0xffffffffu, sq, o);
    }
    __shared__ float ssum[4], ssq[4], sstat[2];
    int wid = tid >> 5, lane = tid & 31;
    if (lane == 0) { ssum[wid] = sum; ssq[wid] = sq; }
    __syncthreads();
    if (tid == 0) {
        float ts = ssum[0] + ssum[1] + ssum[2] + ssum[3];
        float tq = ssq[0] + ssq[1] + ssq[2] + ssq[3];
        float mu = ts * (1.f / 512.f);
        float var = tq * (1.f / 512.f) - mu * mu;
        sstat[0] = mu;
        sstat[1] = rsqrtf(var + 1e-5f);
    }
    __syncthreads();
    float mu = sstat[0], rstd = sstat[1];
    float4 gg = __ldg(&((const float4*)g)[tid]);
    float4 bb = __ldg(&((const float4*)b)[tid]);
    v.x = (v.x - mu) * rstd * gg.x + bb.x;
    v.y = (v.y - mu) * rstd * gg.y + bb.y;
    v.z = (v.z - mu) * rstd * gg.z + bb.z;
    v.w = (v.w - mu) * rstd * gg.w + bb.w;
    xr[tid] = v;
}

// ---------------- zero (float4) ----------------
__global__ void zero_kernel(float* __restrict__ p, int n4)
{
    int i = blockIdx.x * blockDim.x + threadIdx.x;
    if (i < n4) ((float4*)p)[i] = make_float4(0.f, 0.f, 0.f, 0.f);
}

// =====================================================================================
extern "C" void kernel_launch(void* const* d_in, const int* in_sizes, int n_in,
                              void* d_out, int out_size)
{
    const int N = NN, H = HH, E = EE;

    const float* fu0 = (const float*)d_in[0];
    const float* fi1 = (const float*)d_in[3];
    const float* fu2 = (const float*)d_in[4];
    const int* eUI0 = (const int*)d_in[6];
    const int* eIU1 = (const int*)d_in[9];
    const float* Wu   = (const float*)d_in[10];
    const float* bu   = (const float*)d_in[11];
    const float* Wi   = (const float*)d_in[12];
    const float* bi   = (const float*)d_in[13];
    const float* gatW = (const float*)d_in[14];
    const float* gatb = (const float*)d_in[15];
    const float* aw   = (const float*)d_in[16];
    const float* ab   = (const float*)d_in[17];
    const float* gbias= (const float*)d_in[18];
    const float* prepW= (const float*)d_in[19];
    const float* prepb= (const float*)d_in[20];
    const float* dnnW = (const float*)d_in[21];
    const float* dnnb = (const float*)d_in[22];
    const float* lng  = (const float*)d_in[23];
    const float* lnb  = (const float*)d_in[24];
    const float* rlng = (const float*)d_in[25];
    const float* rlnb = (const float*)d_in[26];
    const float* clsW = (const float*)d_in[27];
    const float* clsb = (const float*)d_in[28];

    float *bufA, *bufB, *bufC, *bufD, *bufF, *bufG, *hp, *ssc, *tsc, *den, *ew;
    __nv_bfloat16 *ah, *al, *bth, *btl;
    cudaGetSymbolAddress((void**)&bufA, g_bufA);
    cudaGetSymbolAddress((void**)&bufB, g_bufB);
    cudaGetSymbolAddress((void**)&bufC, g_bufC);
    cudaGetSymbolAddress((void**)&bufD, g_bufD);
    cudaGetSymbolAddress((void**)&bufF, g_bufF);
    cudaGetSymbolAddress((void**)&bufG, g_bufG);
    cudaGetSymbolAddress((void**)&hp,   g_hp);
    cudaGetSymbolAddress((void**)&ssc,  g_ssc);
    cudaGetSymbolAddress((void**)&tsc,  g_tsc);
    cudaGetSymbolAddress((void**)&den,  g_den);
    cudaGetSymbolAddress((void**)&ew,   g_ew);
    cudaGetSymbolAddress((void**)&ah,   g_ah);
    cudaGetSymbolAddress((void**)&al,   g_al);
    cudaGetSymbolAddress((void**)&bth,  g_bth);
    cudaGetSymbolAddress((void**)&btl,  g_btl);

    cudaFuncSetAttribute(tc_gemm, cudaFuncAttributeMaxDynamicSharedMemorySize, GEMM_SMEM);

    dim3 gemmGrid(4, (N + BM - 1) / BM);     // 4 x 157
    const int rowdotBlocks = (N * 32 + 255) / 256;
    const int edgeBlocks = (E + 255) / 256;
    const int scatBlocks = (E * 32 + 255) / 256;
    const int nh4 = N * (H / 4);
    const int zeroHPblocks = (nh4 + 255) / 256;
    const int zeroDenBlocks = ((N / 4) + 255) / 256;

    auto splitA = [&](const float* X, int elems) {
        split_kernel<<<(elems / 4 + 255) / 256, 256>>>(X, ah, al, elems / 4);
    };
    auto splitB = [&](const float* B, int K) {
        splitT_kernel<<<(K * 512 + 255) / 256, 256>>>(B, bth, btl, K, 512);
    };
    auto gemm = [&](const float* bias, float* C, int K, int op) {
        tc_gemm<<<gemmGrid, 256, GEMM_SMEM>>>(ah, al, bth, btl, bias, C, N, K, op);
    };

    // --- deep transforms ---
    splitB(Wu, 512); splitA(fu2, N * 512);
    gemm(bu, bufA, 512, 0);                                   // su_h2
    splitB(Wi, 256); splitA(fi1, N * 256);
    gemm(bi, bufB, 256, 0);                                   // hi_h1

    // --- GAT relation 1 @ hop 1: head=hi_h1, tail=su_h2, edges_IU_h1 ---
    splitB(gatW + H * H, 512);
    splitA(bufB, N * 512); gemm(gatb + H, bufC, 512, 0);      // s1
    splitA(bufA, N * 512); gemm(gatb + H, bufD, 512, 0);      // t1
    rowdot_kernel<<<rowdotBlocks, 256>>>(bufC, aw + 2 * H, nullptr, ssc, N, 0);
    rowdot_kernel<<<rowdotBlocks, 256>>>(bufD, aw + 2 * H + H, nullptr, tsc, N, 0);
    zero_kernel<<<zeroHPblocks, 256>>>(hp, nh4);
    zero_kernel<<<zeroDenBlocks, 256>>>(den, N / 4);
    edge_p1_kernel<<<edgeBlocks, 256>>>(eIU1, eIU1 + E, ssc, tsc, ab, 1, ew, den, E);
    scatter_kernel<<<scatBlocks, 256>>>(eIU1, eIU1 + E, ew, den, bufD, hp, E);
    combine_kernel<<<(nh4 + 255) / 256, 256>>>(bufB, hp, gbias + H, bufF, nh4);  // si_new

    // --- hop 0 ---
    splitB(Wu, 512); splitA(fu0, N * 512);
    gemm(bu, bufG, 512, 0);                                   // hu_h0
    splitB(gatW, 512);
    splitA(bufG, N * 512); gemm(gatb, bufC, 512, 0);          // s0
    splitA(bufF, N * 512); gemm(gatb, bufD, 512, 0);          // t0
    rowdot_kernel<<<rowdotBlocks, 256>>>(bufC, aw, nullptr, ssc, N, 0);
    rowdot_kernel<<<rowdotBlocks, 256>>>(bufD, aw + H, nullptr, tsc, N, 0);
    zero_kernel<<<zeroHPblocks, 256>>>(hp, nh4);
    zero_kernel<<<zeroDenBlocks, 256>>>(den, N / 4);
    edge_p1_kernel<<<edgeBlocks, 256>>>(eUI0, eUI0 + E, ssc, tsc, ab, 0, ew, den, E);
    scatter_kernel<<<scatBlocks, 256>>>(eUI0, eUI0 + E, ew, den, bufD, hp, E);
    combine_kernel<<<(nh4 + 255) / 256, 256>>>(bufG, hp, gbias, bufA, nh4);      // su_final

    // --- Res_DNN head ---
    splitB(prepW, 512); splitA(bufA, N * 512);
    gemm(prepb, bufB, 512, 0);                                // x
    for (int r = 0; r < 2; r++) {
        splitB(dnnW + (size_t)(r * 2 + 0) * H * H, 512);
        splitA(bufB, N * 512);
        gemm(dnnb + (r * 2 + 0) * H, bufC, 512, 1);
        ln_kernel<<<N, 128>>>(bufC, nullptr, lng + (r * 2 + 0) * H, lnb + (r * 2 + 0) * H, 0);
        splitB(dnnW + (size_t)(r * 2 + 1) * H * H, 512);
        splitA(bufC, N * 512);
        gemm(dnnb + (r * 2 + 1) * H, bufD, 512, 1);
        ln_kernel<<<N, 128>>>(bufD, nullptr, lng + (r * 2 + 1) * H, lnb + (r * 2 + 1) * H, 0);
        ln_kernel<<<N, 128>>>(bufB, bufD, rlng + r * H, rlnb + r * H, 1);        // x = LN(tanh(sc+x))
    }

    // --- classifier + sigmoid ---
    rowdot_kernel<<<rowdotBlocks, 256>>>(bufB, clsW, clsb, (float*)d_out, N, 1);
}

// round 5
// speedup vs baseline: 2.6037x; 1.1736x over previous
#include <cuda_runtime.h>
#include <cuda_bf16.h>
#include <math.h>
#include <stdint.h>

#define NN 20000
#define HH 512
#define EE 200000

// ---------------- scratch (static device globals; no allocation) ----------------
__device__ float g_bufA[NN * HH];
__device__ float g_bufB[NN * HH];
__device__ float g_bufC[NN * HH];
__device__ float g_bufD[NN * HH];
__device__ float g_bufF[NN * HH];
__device__ float g_bufG[NN * HH];
__device__ float g_hp[NN * HH];
__device__ float g_ssc[NN];
__device__ float g_tsc[NN];
__device__ float g_den[NN];
__device__ float g_ew[EE];
__device__ float g_ws[513];                 // folded s-side attention vector (+const)
__device__ float g_wt[513];                 // folded t-side attention vector (+const)
__device__ __nv_bfloat16 g_ah[NN * HH];     // A split hi  [M,K]
__device__ __nv_bfloat16 g_al[NN * HH];     // A split lo
__device__ __nv_bfloat16 g_bth[HH * HH];    // B^T split hi [512,K]
__device__ __nv_bfloat16 g_btl[HH * HH];    // B^T split lo

// ======================= portable tensor-core GEMM (mma.sync bf16x3) =======================
// C[M,512] = A[M,K] @ W[K,512] + bias; Ah*Bh + Ah*Bl + Al*Bh, f32 accum.
// Block 128x128, BK=32, 8 warps (warp tile 64x32), cp.async double buffer, ldmatrix loads.

#define BM 128
#define BN 128
#define BK 32
#define PAD 40                       // padded K-stride in halves (80B -> conflict-free ldmatrix)
#define MAT_HALVES (BM * PAD)
#define STAGE_BYTES (4 * MAT_HALVES * 2)   // Ah|Al|Bh|Bl = 40960 B
#define GEMM_SMEM (2 * STAGE_BYTES)        // 81920 B

__device__ __forceinline__ void cp16(uint32_t saddr, const void* gptr) {
    asm volatile("cp.async.cg.shared.global [%0], [%1], 16;" :: "r"(saddr), "l"(gptr));
}
__device__ __forceinline__ void cp_commit() { asm volatile("cp.async.commit_group;"); }
template <int N> __device__ __forceinline__ void cp_wait() {
    asm volatile("cp.async.wait_group %0;" :: "n"(N));
}
__device__ __forceinline__ void ldsm4(uint32_t* r, uint32_t addr) {
    asm volatile("ldmatrix.sync.aligned.m8n8.x4.shared.b16 {%0,%1,%2,%3}, [%4];"
                 : "=r"(r[0]), "=r"(r[1]), "=r"(r[2]), "=r"(r[3]) : "r"(addr));
}
__device__ __forceinline__ void mma16816(float* c, const uint32_t* a, uint32_t b0, uint32_t b1) {
    asm volatile(
        "mma.sync.aligned.m16n8k16.row.col.f32.bf16.bf16.f32 "
        "{%0,%1,%2,%3}, {%4,%5,%6,%7}, {%8,%9}, {%0,%1,%2,%3};"
        : "+f"(c[0]), "+f"(c[1]), "+f"(c[2]), "+f"(c[3])
        : "r"(a[0]), "r"(a[1]), "r"(a[2]), "r"(a[3]), "r"(b0), "r"(b1));
}

__global__ __launch_bounds__(256, 2)
void tc_gemm(const __nv_bfloat16* __restrict__ Ah, const __nv_bfloat16* __restrict__ Al,
             const __nv_bfloat16* __restrict__ Bh, const __nv_bfloat16* __restrict__ Bl,
             const float* __restrict__ bias, float* __restrict__ C,
             __nv_bfloat16* __restrict__ oh, __nv_bfloat16* __restrict__ ol,
             int M, int K, int op)
{
    extern __shared__ __nv_bfloat16 sm[];
    const int tid = threadIdx.x;
    const int wid = tid >> 5;
    const int lane = tid & 31;
    const int rowBase = blockIdx.y * BM;
    const int colBase = blockIdx.x * BN;
    const int nChunks = K >> 5;

    const int m_base = (wid & 1) * 64;
    const int n_base = (wid >> 1) * 32;

    const uint32_t smemBase = (uint32_t)__cvta_generic_to_shared(sm);

    float acc[4][4][4];
#pragma unroll
    for (int mi = 0; mi < 4; mi++)
#pragma unroll
        for (int nj = 0; nj < 4; nj++)
#pragma unroll
            for (int r = 0; r < 4; r++) acc[mi][nj][r] = 0.f;

    auto loadStage = [&](int s, int k0) {
        uint32_t st = smemBase + s * STAGE_BYTES;
#pragma unroll
        for (int i = 0; i < 2; i++) {
            int chunk = tid + i * 256;
            int r = chunk >> 2;
            int seg = chunk & 3;
            uint32_t dst = st + (uint32_t)(r * PAD + seg * 8) * 2;
            int grow = rowBase + r; if (grow > M - 1) grow = M - 1;
            size_t aoff = (size_t)grow * K + k0 + seg * 8;
            cp16(dst, Ah + aoff);
            cp16(dst + MAT_HALVES * 2, Al + aoff);
            int gn = colBase + r;
            size_t boff = (size_t)gn * K + k0 + seg * 8;
            cp16(dst + 2 * MAT_HALVES * 2, Bh + boff);
            cp16(dst + 3 * MAT_HALVES * 2, Bl + boff);
        }
    };

    // ldmatrix lane geometry
    const int lr = lane & 7;
    const int lg = lane >> 3;
    const uint32_t aRowOff = (uint32_t)((lg & 1) * 8 + lr) * PAD + (uint32_t)(lg >> 1) * 8;

    loadStage(0, 0);
    cp_commit();

    for (int c = 0; c < nChunks; c++) {
        int s = c & 1;
        if (c + 1 < nChunks) { loadStage((c + 1) & 1, (c + 1) * BK); cp_commit(); cp_wait<1>(); }
        else cp_wait<0>();
        __syncthreads();

        uint32_t base = smemBase + s * STAGE_BYTES;
        uint32_t baseAh = base;
        uint32_t baseAl = base + MAT_HALVES * 2;
        uint32_t baseBh = base + 2 * MAT_HALVES * 2;
        uint32_t baseBl = base + 3 * MAT_HALVES * 2;

#pragma unroll
        for (int kk = 0; kk < BK; kk += 16) {
            // B fragments: 4 n8-tiles, hi+lo
            uint32_t bh[4][2], bl[4][2];
#pragma unroll
            for (int p = 0; p < 2; p++) {
                uint32_t off = ((uint32_t)(n_base + p * 16 + (lg & 1) * 8 + lr) * PAD
                                + kk + (lg >> 1) * 8) * 2;
                uint32_t t[4];
                ldsm4(t, baseBh + off);
                bh[2 * p][0] = t[0]; bh[2 * p][1] = t[2];
                bh[2 * p + 1][0] = t[1]; bh[2 * p + 1][1] = t[3];
                ldsm4(t, baseBl + off);
                bl[2 * p][0] = t[0]; bl[2 * p][1] = t[2];
                bl[2 * p + 1][0] = t[1]; bl[2 * p + 1][1] = t[3];
            }
            // A fragments streamed per mi
#pragma unroll
            for (int mi = 0; mi < 4; mi++) {
                uint32_t off = (aRowOff + (uint32_t)(m_base + mi * 16) * PAD + kk) * 2;
                uint32_t af[4], afl[4];
                ldsm4(af, baseAh + off);
                ldsm4(afl, baseAl + off);
#pragma unroll
                for (int nj = 0; nj < 4; nj++) {
                    mma16816(acc[mi][nj], af, bh[nj][0], bh[nj][1]);
                    mma16816(acc[mi][nj], af, bl[nj][0], bl[nj][1]);
                    mma16816(acc[mi][nj], afl, bh[nj][0], bh[nj][1]);
                }
            }
        }
        __syncthreads();
    }

    // ---- epilogue: bias + optional tanh + optional fused bf16 split ----
#pragma unroll
    for (int mi = 0; mi < 4; mi++) {
        int row0 = rowBase + m_base + mi * 16 + (lane >> 2);
        int row1 = row0 + 8;
#pragma unroll
        for (int nj = 0; nj < 4; nj++) {
            int col = colBase + n_base + nj * 8 + (lane & 3) * 2;
            float b0 = __ldg(bias + col), b1 = __ldg(bias + col + 1);
            float2 v0 = make_float2(acc[mi][nj][0] + b0, acc[mi][nj][1] + b1);
            float2 v1 = make_float2(acc[mi][nj][2] + b0, acc[mi][nj][3] + b1);
            if (op == 1) {
                v0.x = tanhf(v0.x); v0.y = tanhf(v0.y);
                v1.x = tanhf(v1.x); v1.y = tanhf(v1.y);
            }
            if (row0 < M) {
                *(float2*)(C + (size_t)row0 * 512 + col) = v0;
                if (oh) {
                    __nv_bfloat16 h0 = __float2bfloat16(v0.x), h1 = __float2bfloat16(v0.y);
                    *(__nv_bfloat162*)(oh + (size_t)row0 * 512 + col) = __nv_bfloat162(h0, h1);
                    *(__nv_bfloat162*)(ol + (size_t)row0 * 512 + col) =
                        __nv_bfloat162(__float2bfloat16(v0.x - __bfloat162float(h0)),
                                       __float2bfloat16(v0.y - __bfloat162float(h1)));
                }
            }
            if (row1 < M) {
                *(float2*)(C + (size_t)row1 * 512 + col) = v1;
                if (oh) {
                    __nv_bfloat16 h0 = __float2bfloat16(v1.x), h1 = __float2bfloat16(v1.y);
                    *(__nv_bfloat162*)(oh + (size_t)row1 * 512 + col) = __nv_bfloat162(h0, h1);
                    *(__nv_bfloat162*)(ol + (size_t)row1 * 512 + col) =
                        __nv_bfloat162(__float2bfloat16(v1.x - __bfloat162float(h0)),
                                       __float2bfloat16(v1.y - __bfloat162float(h1)));
                }
            }
        }
    }
}

// ---------------- split fp32 -> bf16 hi/lo (elementwise, float4) ----------------
__global__ void split_kernel(const float* __restrict__ X, __nv_bfloat16* __restrict__ h,
                             __nv_bfloat16* __restrict__ l, int n4)
{
    int i = blockIdx.x * blockDim.x + threadIdx.x;
    if (i >= n4) return;
    float4 x = ((const float4*)X)[i];
    __nv_bfloat16 h0 = __float2bfloat16(x.x), h1 = __float2bfloat16(x.y);
    __nv_bfloat16 h2 = __float2bfloat16(x.z), h3 = __float2bfloat16(x.w);
    __nv_bfloat162* hp2 = (__nv_bfloat162*)h;
    __nv_bfloat162* lp2 = (__nv_bfloat162*)l;
    hp2[i * 2 + 0] = __nv_bfloat162(h0, h1);
    hp2[i * 2 + 1] = __nv_bfloat162(h2, h3);
    lp2[i * 2 + 0] = __nv_bfloat162(__float2bfloat16(x.x - __bfloat162float(h0)),
                                    __float2bfloat16(x.y - __bfloat162float(h1)));
    lp2[i * 2 + 1] = __nv_bfloat162(__float2bfloat16(x.z - __bfloat162float(h2)),
                                    __float2bfloat16(x.w - __bfloat162float(h3)));
}

// ------------- transpose + split weights: B[K,N] fp32 -> Bt hi/lo [N,K] bf16 -------------
__global__ void splitT_kernel(const float* __restrict__ B, __nv_bfloat16* __restrict__ th,
                              __nv_bfloat16* __restrict__ tl, int K, int Ncols)
{
    int idx = blockIdx.x * blockDim.x + threadIdx.x;
    if (idx >= K * Ncols) return;
    int n = idx / K, k = idx - n * K;
    float x = B[(size_t)k * Ncols + n];
    __nv_bfloat16 hi = __float2bfloat16(x);
    th[idx] = hi;
    tl[idx] = __float2bfloat16(x - __bfloat162float(hi));
}

// -------- fold attention vector into feature weights: w'[k]=sum_j fW[k][j]*aw[j]; w'[512]=fb.aw
__global__ void prepw_kernel(const float* __restrict__ fW, const float* __restrict__ fb,
                             const float* __restrict__ aw, float* __restrict__ out)
{
    int k = blockIdx.x * blockDim.x + threadIdx.x;
    if (k > 512) return;
    const float* row = (k < 512) ? (fW + (size_t)k * 512) : fb;
    float s = 0.f;
    const float4* r4 = (const float4*)row;
    const float4* a4 = (const float4*)aw;
#pragma unroll 4
    for (int j = 0; j < 128; j++) {
        float4 a = __ldg(&r4[j]);
        float4 b = __ldg(&a4[j]);
        s += a.x * b.x + a.y * b.y + a.z * b.z + a.w * b.w;
    }
    out[k] = s;
}

// ---------------- per-row dot: out[r] = X[r,:] . v  (mode1: sigmoid(+bias)) -----
__global__ void rowdot_kernel(const float* __restrict__ X, const float* __restrict__ v,
                              const float* __restrict__ bptr, float* __restrict__ out,
                              int n, int mode)
{
    int w = (blockIdx.x * blockDim.x + threadIdx.x) >> 5;
    int lane = threadIdx.x & 31;
    if (w >= n) return;
    const float4* xr = ((const float4*)X) + (size_t)w * 128;
    const float4* vr = (const float4*)v;
    float s = 0.f;
#pragma unroll
    for (int i = 0; i < 4; i++) {
        float4 a = xr[lane + 32 * i];
        float4 b = __ldg(&vr[lane + 32 * i]);
        s += a.x * b.x + a.y * b.y + a.z * b.z + a.w * b.w;
    }
#pragma unroll
    for (int o = 16; o > 0; o >>= 1) s += __shfl_xor_sync(0xffffffffu, s, o);
    if (lane == 0) {
        if (mode == 1) out[w] = 1.f / (1.f + expf(-(s + bptr[0])));
        else out[w] = s;
    }
}

// ---------------- edge pass: ew=exp(tanh(ssc[s]+tsc[t]+cs+ct+ab)), den[s]+= ------
__global__ void edge_p1_kernel(const int* __restrict__ src, const int* __restrict__ tgt,
                               const float* __restrict__ ssc, const float* __restrict__ tsc,
                               const float* __restrict__ cs, const float* __restrict__ ct,
                               const float* __restrict__ abptr, int abidx,
                               float* __restrict__ ew, float* __restrict__ den, int E)
{
    int i = blockIdx.x * blockDim.x + threadIdx.x;
    if (i >= E) return;
    float e = tanhf(ssc[src[i]] + tsc[tgt[i]] + cs[0] + ct[0] + abptr[abidx]);
    float x = expf(e);
    ew[i] = x;
    atomicAdd(&den[src[i]], x);
}

// ---------------- scatter (warp per edge, float4 vector atomics) -----------
__global__ void scatter_kernel(const int* __restrict__ src, const int* __restrict__ tgt,
                               const float* __restrict__ ew, const float* __restrict__ den,
                               const float* __restrict__ t, float* __restrict__ hp, int E)
{
    int e = (blockIdx.x * blockDim.x + threadIdx.x) >> 5;
    int lane = threadIdx.x & 31;
    if (e >= E) return;
    int s = src[e], g = tgt[e];
    float alpha = ew[e] / den[s];
    const float4* tr = ((const float4*)t) + (size_t)g * 128;
    float4* hr = ((float4*)(hp + (size_t)s * 512));
#pragma unroll
    for (int i = 0; i < 4; i++) {
        float4 v = tr[lane + 32 * i];
        float4 w = make_float4(v.x * alpha, v.y * alpha, v.z * alpha, v.w * alpha);
        atomicAdd(hr + lane + 32 * i, w);
    }
}

// ---------------- combine: out = (h + hp + gbias)*0.5 (+ optional split) -------
__global__ void combine_kernel(const float* __restrict__ h, const float* __restrict__ hp,
                               const float* __restrict__ gb, float* __restrict__ out,
                               __nv_bfloat16* __restrict__ oh, __nv_bfloat16* __restrict__ ol,
                               int total4)
{
    int i = blockIdx.x * blockDim.x + threadIdx.x;
    if (i >= total4) return;
    float4 a = ((const float4*)h)[i];
    float4 c = ((const float4*)hp)[i];
    float4 g = __ldg(&((const float4*)gb)[i & 127]);
    float4 r;
    r.x = (a.x + c.x + g.x) * 0.5f;
    r.y = (a.y + c.y + g.y) * 0.5f;
    r.z = (a.z + c.z + g.z) * 0.5f;
    r.w = (a.w + c.w + g.w) * 0.5f;
    ((float4*)out)[i] = r;
    if (oh) {
        __nv_bfloat16 h0 = __float2bfloat16(r.x), h1 = __float2bfloat16(r.y);
        __nv_bfloat16 h2 = __float2bfloat16(r.z), h3 = __float2bfloat16(r.w);
        ((__nv_bfloat162*)oh)[i * 2 + 0] = __nv_bfloat162(h0, h1);
        ((__nv_bfloat162*)oh)[i * 2 + 1] = __nv_bfloat162(h2, h3);
        ((__nv_bfloat162*)ol)[i * 2 + 0] =
            __nv_bfloat162(__float2bfloat16(r.x - __bfloat162float(h0)),
                           __float2bfloat16(r.y - __bfloat162float(h1)));
        ((__nv_bfloat162*)ol)[i * 2 + 1] =
            __nv_bfloat162(__float2bfloat16(r.z - __bfloat162float(h2)),
                           __float2bfloat16(r.w - __bfloat162float(h3)));
    }
}

// ------------- layernorm in place (mode1: v=tanh(x+x2) first) + optional split -------------
__global__ void ln_kernel(float* __restrict__ x, const float* __restrict__ x2,
                          const float* __restrict__ g, const float* __restrict__ b,
                          __nv_bfloat16* __restrict__ oh, __nv_bfloat16* __restrict__ ol,
                          int mode)
{
    int row = blockIdx.x;
    int tid = threadIdx.x;
    float4* xr = ((float4*)x) + (size_t)row * 128;
    float4 v = xr[tid];
    if (mode == 1) {
        float4 w = ((const float4*)x2)[(size_t)row * 128 + tid];
        v.x = tanhf(v.x + w.x); v.y = tanhf(v.y + w.y);
        v.z = tanhf(v.z + w.z); v.w = tanhf(v.w + w.w);
    }
    float sum = v.x + v.y + v.z + v.w;
    float sq  = v.x * v.x + v.y * v.y + v.z * v.z + v.w * v.w;
#pragma unroll
    for (int o = 16; o > 0; o >>= 1) {
        sum += __shfl_xor_sync(0xffffffffu, sum, o);
        sq  += __shfl_xor_sync(0xffffffffu, sq, o);
    }
    __shared__ float ssum[4], ssq[4], sstat[2];
    int wid = tid >> 5, lane = tid & 31;
    if (lane == 0) { ssum[wid] = sum; ssq[wid] = sq; }
    __syncthreads();
    if (tid == 0) {
        float ts = ssum[0] + ssum[1] + ssum[2] + ssum[3];
        float tq = ssq[0] + ssq[1] + ssq[2] + ssq[3];
        float mu = ts * (1.f / 512.f);
        float var = tq * (1.f / 512.f) - mu * mu;
        sstat[0] = mu;
        sstat[1] = rsqrtf(var + 1e-5f);
    }
    __syncthreads();
    float mu = sstat[0], rstd = sstat[1];
    float4 gg = __ldg(&((const float4*)g)[tid]);
    float4 bb = __ldg(&((const float4*)b)[tid]);
    v.x = (v.x - mu) * rstd * gg.x + bb.x;
    v.y = (v.y - mu) * rstd * gg.y + bb.y;
    v.z = (v.z - mu) * rstd * gg.z + bb.z;
    v.w = (v.w - mu) * rstd * gg.w + bb.w;
    xr[tid] = v;
    if (oh) {
        size_t o2 = (size_t)row * 256 + tid * 2;
        __nv_bfloat16 h0 = __float2bfloat16(v.x), h1 = __float2bfloat16(v.y);
        __nv_bfloat16 h2 = __float2bfloat16(v.z), h3 = __float2bfloat16(v.w);
        ((__nv_bfloat162*)oh)[o2 + 0] = __nv_bfloat162(h0, h1);
        ((__nv_bfloat162*)oh)[o2 + 1] = __nv_bfloat162(h2, h3);
        ((__nv_bfloat162*)ol)[o2 + 0] =
            __nv_bfloat162(__float2bfloat16(v.x - __bfloat162float(h0)),
                           __float2bfloat16(v.y - __bfloat162float(h1)));
        ((__nv_bfloat162*)ol)[o2 + 1] =
            __nv_bfloat162(__float2bfloat16(v.z - __bfloat162float(h2)),
                           __float2bfloat16(v.w - __bfloat162float(h3)));
    }
}

// ---------------- zero (float4) ----------------
__global__ void zero_kernel(float* __restrict__ p, int n4)
{
    int i = blockIdx.x * blockDim.x + threadIdx.x;
    if (i < n4) ((float4*)p)[i] = make_float4(0.f, 0.f, 0.f, 0.f);
}

// =====================================================================================
extern "C" void kernel_launch(void* const* d_in, const int* in_sizes, int n_in,
                              void* d_out, int out_size)
{
    const int N = NN, H = HH, E = EE;

    const float* fu0 = (const float*)d_in[0];
    const float* fi1 = (const float*)d_in[3];
    const float* fu2 = (const float*)d_in[4];
    const int* eUI0 = (const int*)d_in[6];
    const int* eIU1 = (const int*)d_in[9];
    const float* Wu   = (const float*)d_in[10];
    const float* bu   = (const float*)d_in[11];
    const float* Wi   = (const float*)d_in[12];
    const float* bi   = (const float*)d_in[13];
    const float* gatW = (const float*)d_in[14];
    const float* gatb = (const float*)d_in[15];
    const float* aw   = (const float*)d_in[16];
    const float* ab   = (const float*)d_in[17];
    const float* gbias= (const float*)d_in[18];
    const float* prepW= (const float*)d_in[19];
    const float* prepb= (const float*)d_in[20];
    const float* dnnW = (const float*)d_in[21];
    const float* dnnb = (const float*)d_in[22];
    const float* lng  = (const float*)d_in[23];
    const float* lnb  = (const float*)d_in[24];
    const float* rlng = (const float*)d_in[25];
    const float* rlnb = (const float*)d_in[26];
    const float* clsW = (const float*)d_in[27];
    const float* clsb = (const float*)d_in[28];

    float *bufA, *bufB, *bufC, *bufD, *bufF, *bufG, *hp, *ssc, *tsc, *den, *ew, *ws, *wt;
    __nv_bfloat16 *ah, *al, *bth, *btl;
    cudaGetSymbolAddress((void**)&bufA, g_bufA);
    cudaGetSymbolAddress((void**)&bufB, g_bufB);
    cudaGetSymbolAddress((void**)&bufC, g_bufC);
    cudaGetSymbolAddress((void**)&bufD, g_bufD);
    cudaGetSymbolAddress((void**)&bufF, g_bufF);
    cudaGetSymbolAddress((void**)&bufG, g_bufG);
    cudaGetSymbolAddress((void**)&hp,   g_hp);
    cudaGetSymbolAddress((void**)&ssc,  g_ssc);
    cudaGetSymbolAddress((void**)&tsc,  g_tsc);
    cudaGetSymbolAddress((void**)&den,  g_den);
    cudaGetSymbolAddress((void**)&ew,   g_ew);
    cudaGetSymbolAddress((void**)&ws,   g_ws);
    cudaGetSymbolAddress((void**)&wt,   g_wt);
    cudaGetSymbolAddress((void**)&ah,   g_ah);
    cudaGetSymbolAddress((void**)&al,   g_al);
    cudaGetSymbolAddress((void**)&bth,  g_bth);
    cudaGetSymbolAddress((void**)&btl,  g_btl);

    cudaFuncSetAttribute(tc_gemm, cudaFuncAttributeMaxDynamicSharedMemorySize, GEMM_SMEM);

    dim3 gemmGrid(4, (N + BM - 1) / BM);
    const int rowdotBlocks = (N * 32 + 255) / 256;
    const int edgeBlocks = (E + 255) / 256;
    const int scatBlocks = (E * 32 + 255) / 256;
    const int nh4 = N * (H / 4);
    const int zeroHPblocks = (nh4 + 255) / 256;
    const int zeroDenBlocks = ((N / 4) + 255) / 256;

    auto splitA = [&](const float* X, int elems) {
        split_kernel<<<(elems / 4 + 255) / 256, 256>>>(X, ah, al, elems / 4);
    };
    auto splitB = [&](const float* B, int K) {
        splitT_kernel<<<(K * 512 + 255) / 256, 256>>>(B, bth, btl, K, 512);
    };
    auto gemm = [&](const float* bias, float* C, __nv_bfloat16* oh, __nv_bfloat16* ol,
                    int K, int op) {
        tc_gemm<<<gemmGrid, 256, GEMM_SMEM>>>(ah, al, bth, btl, bias, C, oh, ol, N, K, op);
    };

    // --- node transforms that survive dead-code elimination ---
    splitB(Wu, 512); splitA(fu2, N * 512);
    gemm(bu, bufA, nullptr, nullptr, 512, 0);                 // su_h2  (raw scatter payload)
    splitB(Wi, 256); splitA(fi1, N * 256);
    gemm(bi, bufB, nullptr, nullptr, 256, 0);                 // hi_h1

    // --- GAT rel 1 @ hop 1: head=hi_h1, tail=su_h2, edges_IU_h1 ---
    const float* fW1 = gatW + (size_t)H * H;
    const float* fb1 = gatb + H;
    prepw_kernel<<<5, 128>>>(fW1, fb1, aw + 2 * H, ws);       // folded s-side
    prepw_kernel<<<5, 128>>>(fW1, fb1, aw + 3 * H, wt);       // folded t-side
    rowdot_kernel<<<rowdotBlocks, 256>>>(bufB, ws, nullptr, ssc, N, 0);
    rowdot_kernel<<<rowdotBlocks, 256>>>(bufA, wt, nullptr, tsc, N, 0);
    zero_kernel<<<zeroDenBlocks, 256>>>(den, N / 4);
    edge_p1_kernel<<<edgeBlocks, 256>>>(eIU1, eIU1 + E, ssc, tsc, ws + 512, wt + 512, ab, 1, ew, den, E);
    zero_kernel<<<zeroHPblocks, 256>>>(hp, nh4);
    scatter_kernel<<<scatBlocks, 256>>>(eIU1, eIU1 + E, ew, den, bufA, hp, E);  // agg of RAW su_h2
    splitA(hp, N * 512); splitB(fW1, 512);
    gemm(fb1, bufD, nullptr, nullptr, 512, 0);                // hp1 = agg @ fW1 + fb1
    combine_kernel<<<(nh4 + 255) / 256, 256>>>(bufB, bufD, gbias + H, bufF, nullptr, nullptr, nh4); // si_new

    // --- GAT rel 0 @ hop 0: head=hu_h0, tail=si_new, edges_UI_h0 ---
    splitB(Wu, 512); splitA(fu0, N * 512);
    gemm(bu, bufG, nullptr, nullptr, 512, 0);                 // hu_h0
    prepw_kernel<<<5, 128>>>(gatW, gatb, aw, ws);
    prepw_kernel<<<5, 128>>>(gatW, gatb, aw + H, wt);
    rowdot_kernel<<<rowdotBlocks, 256>>>(bufG, ws, nullptr, ssc, N, 0);
    rowdot_kernel<<<rowdotBlocks, 256>>>(bufF, wt, nullptr, tsc, N, 0);
    zero_kernel<<<zeroDenBlocks, 256>>>(den, N / 4);
    edge_p1_kernel<<<edgeBlocks, 256>>>(eUI0, eUI0 + E, ssc, tsc, ws + 512, wt + 512, ab, 0, ew, den, E);
    zero_kernel<<<zeroHPblocks, 256>>>(hp, nh4);
    scatter_kernel<<<scatBlocks, 256>>>(eUI0, eUI0 + E, ew, den, bufF, hp, E);  // agg of RAW si_new
    splitA(hp, N * 512); splitB(gatW, 512);
    gemm(gatb, bufD, nullptr, nullptr, 512, 0);               // hp0 = agg @ fW0 + fb0
    combine_kernel<<<(nh4 + 255) / 256, 256>>>(bufG, bufD, gbias, bufA, ah, al, nh4); // su_final (+split)

    // --- Res_DNN head (inputs flow through fused splits) ---
    splitB(prepW, 512);
    gemm(prepb, bufB, ah, al, 512, 0);                        // x = su_final @ prepW + b (+split)
    for (int r = 0; r < 2; r++) {
        splitB(dnnW + (size_t)(r * 2 + 0) * H * H, 512);
        gemm(dnnb + (r * 2 + 0) * H, bufC, nullptr, nullptr, 512, 1);
        ln_kernel<<<N, 128>>>(bufC, nullptr, lng + (r * 2 + 0) * H, lnb + (r * 2 + 0) * H, ah, al, 0);
        splitB(dnnW + (size_t)(r * 2 + 1) * H * H, 512);
        gemm(dnnb + (r * 2 + 1) * H, bufD, nullptr, nullptr, 512, 1);
        ln_kernel<<<N, 128>>>(bufD, nullptr, lng + (r * 2 + 1) * H, lnb + (r * 2 + 1) * H, nullptr, nullptr, 0);
        // x = LN(tanh(sc + x)); split only needed when feeding next dnn GEMM
        ln_kernel<<<N, 128>>>(bufB, bufD, rlng + r * H, rlnb + r * H,
                              (r == 0) ? ah : nullptr, (r == 0) ? al : nullptr, 1);
    }

    // --- classifier + sigmoid ---
    rowdot_kernel<<<rowdotBlocks, 256>>>(bufB, clsW, clsb, (float*)d_out, N, 1);
}

// round 9
// speedup vs baseline: 2.6922x; 1.0340x over previous
#include <cuda_runtime.h>
#include <cuda_bf16.h>
#include <math.h>
#include <stdint.h>

#define NN 20000
#define HH 512
#define EE 200000

// ---------------- scratch (static device globals; no allocation) ----------------
__device__ float g_bufA[NN * HH];
__device__ float g_bufB[NN * HH];
__device__ float g_bufC[NN * HH];
__device__ float g_bufD[NN * HH];
__device__ float g_bufF[NN * HH];
__device__ float g_bufG[NN * HH];
__device__ float g_hp[NN * HH];
__device__ float g_ssc[NN];
__device__ float g_tsc[NN];
__device__ float g_den[NN];
__device__ float g_ew[EE];
__device__ float g_ws[513];
__device__ float g_wt[513];
__device__ __nv_bfloat16 g_bth0[HH * HH];   // weight split pair 0 (hi)  [512 rows, K]
__device__ __nv_bfloat16 g_btl0[HH * HH];   // weight split pair 0 (lo)
__device__ __nv_bfloat16 g_bth1[HH * HH];   // weight split pair 1 (hi)
__device__ __nv_bfloat16 g_btl1[HH * HH];   // weight split pair 1 (lo)

// ======================= tensor-core GEMM (mma.sync bf16x3, fp32 A input) =======================
// C[M,512] = A[M,K] @ W[K,512] + bias.  A arrives fp32; split to bf16 hi/lo in-kernel.
// Block 128x128, BK=32, 8 warps (warp tile 64x32), cp.async double buffer, ldmatrix.
// op: 0 = bias; 1 = bias+tanh; 2 = fused combine: out = (h + acc + bias + gvec) * 0.5

#define BM 128
#define BN 128
#define BK 32
#define PAD 40
#define AH_OFF 0
#define BH_OFF 10240
#define BL_OFF 20480
#define STG_OFF 30720                      // fp32 staging; reused as A-lo bf16 after convert
#define STAGE_BYTES 47104
#define GEMM_SMEM (2 * STAGE_BYTES)        // 94208 B -> occupancy 2

__device__ __forceinline__ void cp16(uint32_t saddr, const void* gptr) {
    asm volatile("cp.async.cg.shared.global [%0], [%1], 16;" :: "r"(saddr), "l"(gptr));
}
__device__ __forceinline__ void cp_commit() { asm volatile("cp.async.commit_group;"); }
template <int N> __device__ __forceinline__ void cp_wait() {
    asm volatile("cp.async.wait_group %0;" :: "n"(N));
}
__device__ __forceinline__ void ldsm4(uint32_t* r, uint32_t addr) {
    asm volatile("ldmatrix.sync.aligned.m8n8.x4.shared.b16 {%0,%1,%2,%3}, [%4];"
                 : "=r"(r[0]), "=r"(r[1]), "=r"(r[2]), "=r"(r[3]) : "r"(addr));
}
__device__ __forceinline__ void mma16816(float* c, const uint32_t* a, uint32_t b0, uint32_t b1) {
    asm volatile(
        "mma.sync.aligned.m16n8k16.row.col.f32.bf16.bf16.f32 "
        "{%0,%1,%2,%3}, {%4,%5,%6,%7}, {%8,%9}, {%0,%1,%2,%3};"
        : "+f"(c[0]), "+f"(c[1]), "+f"(c[2]), "+f"(c[3])
        : "r"(a[0]), "r"(a[1]), "r"(a[2]), "r"(a[3]), "r"(b0), "r"(b1));
}
__device__ __forceinline__ uint32_t pack_bf2(float a, float b) {
    __nv_bfloat162 h = __nv_bfloat162(__float2bfloat16(a), __float2bfloat16(b));
    return *(uint32_t*)&h;
}

__global__ __launch_bounds__(256, 2)
void tc_gemm(const float* __restrict__ A,
             const __nv_bfloat16* __restrict__ Bh, const __nv_bfloat16* __restrict__ Bl,
             const float* __restrict__ bias, const float* __restrict__ hsrc,
             const float* __restrict__ gvec, float* __restrict__ C,
             int M, int K, int op)
{
    extern __shared__ char sm[];
    const int tid = threadIdx.x;
    const int wid = tid >> 5;
    const int lane = tid & 31;
    const int rowBase = blockIdx.y * BM;
    const int colBase = blockIdx.x * BN;
    const int nChunks = K >> 5;

    const int m_base = (wid & 1) * 64;
    const int n_base = (wid >> 1) * 32;
    const uint32_t smemBase = (uint32_t)__cvta_generic_to_shared(sm);

    float acc[4][4][4];
#pragma unroll
    for (int mi = 0; mi < 4; mi++)
#pragma unroll
        for (int nj = 0; nj < 4; nj++)
#pragma unroll
            for (int r = 0; r < 4; r++) acc[mi][nj][r] = 0.f;

    // ---- stage loader: B (bf16 hi/lo) + A (fp32 staging), all cp.async ----
    auto loadStage = [&](int s, int k0) {
        uint32_t st = smemBase + s * STAGE_BYTES;
#pragma unroll
        for (int i = 0; i < 2; i++) {                 // B: 512 chunks x2 matrices
            int chunk = tid + i * 256;
            int r = chunk >> 2, seg = chunk & 3;
            uint32_t d = st + (uint32_t)(r * PAD + seg * 8) * 2;
            size_t boff = (size_t)(colBase + r) * K + k0 + seg * 8;
            cp16(d + BH_OFF, Bh + boff);
            cp16(d + BL_OFF, Bl + boff);
        }
#pragma unroll
        for (int i = 0; i < 4; i++) {                 // A fp32: 1024 chunks of 16B
            int chunk = tid + i * 256;
            int r = chunk >> 3, seg = chunk & 7;
            int grow = rowBase + r; if (grow > M - 1) grow = M - 1;
            cp16(st + STG_OFF + (uint32_t)(r * 128 + seg * 16),
                 A + (size_t)grow * K + k0 + seg * 4);
        }
    };

    // ---- convert own-loaded fp32 A chunks -> bf16 hi (AH) / lo (back into staging) ----
    auto convertA = [&](int s) {
        char* st = sm + s * STAGE_BYTES;
        uint32_t lo[4][2];
        uint32_t dst[4];
#pragma unroll
        for (int i = 0; i < 4; i++) {
            int chunk = tid + i * 256;
            int r = chunk >> 3, seg = chunk & 7;
            float4 v = *(const float4*)(st + STG_OFF + r * 128 + seg * 16);
            uint32_t hi0 = pack_bf2(v.x, v.y), hi1 = pack_bf2(v.z, v.w);
            __nv_bfloat162 h01 = *(__nv_bfloat162*)&hi0;
            __nv_bfloat162 h23 = *(__nv_bfloat162*)&hi1;
            lo[i][0] = pack_bf2(v.x - __bfloat162float(h01.x), v.y - __bfloat162float(h01.y));
            lo[i][1] = pack_bf2(v.z - __bfloat162float(h23.x), v.w - __bfloat162float(h23.y));
            uint32_t off = (uint32_t)(r * PAD + seg * 4) * 2;
            *(uint2*)(st + AH_OFF + off) = make_uint2(hi0, hi1);
            dst[i] = off;
        }
        __syncthreads();                 // all staging reads done before lo overwrites
#pragma unroll
        for (int i = 0; i < 4; i++)
            *(uint2*)(st + STG_OFF + dst[i]) = make_uint2(lo[i][0], lo[i][1]);
    };

    const int lr = lane & 7;
    const int lg = lane >> 3;
    const uint32_t aRowOff = (uint32_t)((lg & 1) * 8 + lr) * PAD + (uint32_t)(lg >> 1) * 8;

    loadStage(0, 0);
    cp_commit();

    for (int c = 0; c < nChunks; c++) {
        int s = c & 1;
        if (c + 1 < nChunks) { loadStage(s ^ 1, (c + 1) * BK); cp_commit(); cp_wait<1>(); }
        else cp_wait<0>();
        convertA(s);
        __syncthreads();                 // hi/lo + B visible to all warps

        uint32_t base = smemBase + s * STAGE_BYTES;
        uint32_t baseAh = base + AH_OFF;
        uint32_t baseAl = base + STG_OFF;
        uint32_t baseBh = base + BH_OFF;
        uint32_t baseBl = base + BL_OFF;

#pragma unroll
        for (int kk = 0; kk < BK; kk += 16) {
            uint32_t bh[4][2], bl[4][2];
#pragma unroll
            for (int p = 0; p < 2; p++) {
                uint32_t off = ((uint32_t)(n_base + p * 16 + (lg & 1) * 8 + lr) * PAD
                                + kk + (lg >> 1) * 8) * 2;
                uint32_t t[4];
                ldsm4(t, baseBh + off);
                bh[2 * p][0] = t[0]; bh[2 * p][1] = t[2];
                bh[2 * p + 1][0] = t[1]; bh[2 * p + 1][1] = t[3];
                ldsm4(t, baseBl + off);
                bl[2 * p][0] = t[0]; bl[2 * p][1] = t[2];
                bl[2 * p + 1][0] = t[1]; bl[2 * p + 1][1] = t[3];
            }
#pragma unroll
            for (int mi = 0; mi < 4; mi++) {
                uint32_t off = (aRowOff + (uint32_t)(m_base + mi * 16) * PAD + kk) * 2;
                uint32_t af[4], afl[4];
                ldsm4(af, baseAh + off);
                ldsm4(afl, baseAl + off);
#pragma unroll
                for (int nj = 0; nj < 4; nj++) {
                    mma16816(acc[mi][nj], af, bh[nj][0], bh[nj][1]);
                    mma16816(acc[mi][nj], af, bl[nj][0], bl[nj][1]);
                    mma16816(acc[mi][nj], afl, bh[nj][0], bh[nj][1]);
                }
            }
        }
        __syncthreads();                 // stage reuse barrier
    }

    // ---- epilogue ----
#pragma unroll
    for (int mi = 0; mi < 4; mi++) {
        int row0 = rowBase + m_base + mi * 16 + (lane >> 2);
        int row1 = row0 + 8;
#pragma unroll
        for (int nj = 0; nj < 4; nj++) {
            int col = colBase + n_base + nj * 8 + (lane & 3) * 2;
            float b0 = __ldg(bias + col), b1 = __ldg(bias + col + 1);
            float2 v0 = make_float2(acc[mi][nj][0] + b0, acc[mi][nj][1] + b1);
            float2 v1 = make_float2(acc[mi][nj][2] + b0, acc[mi][nj][3] + b1);
            if (op == 1) {
                v0.x = tanhf(v0.x); v0.y = tanhf(v0.y);
                v1.x = tanhf(v1.x); v1.y = tanhf(v1.y);
            } else if (op == 2) {
                float g0 = __ldg(gvec + col), g1 = __ldg(gvec + col + 1);
                if (row0 < M) {
                    float2 h = *(const float2*)(hsrc + (size_t)row0 * 512 + col);
                    v0.x = (h.x + v0.x + g0) * 0.5f;
                    v0.y = (h.y + v0.y + g1) * 0.5f;
                }
                if (row1 < M) {
                    float2 h = *(const float2*)(hsrc + (size_t)row1 * 512 + col);
                    v1.x = (h.x + v1.x + g0) * 0.5f;
                    v1.y = (h.y + v1.y + g1) * 0.5f;
                }
            }
            if (row0 < M) *(float2*)(C + (size_t)row0 * 512 + col) = v0;
            if (row1 < M) *(float2*)(C + (size_t)row1 * 512 + col) = v1;
        }
    }
}

// ------------- transpose + split weights: B[K,N] fp32 -> Bt hi/lo [N,K] bf16 -------------
__global__ void splitT_kernel(const float* __restrict__ B, __nv_bfloat16* __restrict__ th,
                              __nv_bfloat16* __restrict__ tl, int K, int Ncols)
{
    int idx = blockIdx.x * blockDim.x + threadIdx.x;
    if (idx >= K * Ncols) return;
    int n = idx / K, k = idx - n * K;
    float x = B[(size_t)k * Ncols + n];
    __nv_bfloat16 hi = __float2bfloat16(x);
    th[idx] = hi;
    tl[idx] = __float2bfloat16(x - __bfloat162float(hi));
}

// -------- fold attention vector into feature weights: w'[k]=fW[k,:].aw; w'[512]=fb.aw --------
__global__ void prepw_kernel(const float* __restrict__ fW, const float* __restrict__ fb,
                             const float* __restrict__ aw, float* __restrict__ out)
{
    int k = blockIdx.x * blockDim.x + threadIdx.x;
    if (k > 512) return;
    const float* row = (k < 512) ? (fW + (size_t)k * 512) : fb;
    float s = 0.f;
    const float4* r4 = (const float4*)row;
    const float4* a4 = (const float4*)aw;
#pragma unroll 4
    for (int j = 0; j < 128; j++) {
        float4 a = __ldg(&r4[j]);
        float4 b = __ldg(&a4[j]);
        s += a.x * b.x + a.y * b.y + a.z * b.z + a.w * b.w;
    }
    out[k] = s;
}

// ---------------- per-row dot: out[r] = X[r,:] . v  (mode1: sigmoid(+bias)) -----
__global__ void rowdot_kernel(const float* __restrict__ X, const float* __restrict__ v,
                              const float* __restrict__ bptr, float* __restrict__ out,
                              int n, int mode)
{
    int w = (blockIdx.x * blockDim.x + threadIdx.x) >> 5;
    int lane = threadIdx.x & 31;
    if (w >= n) return;
    const float4* xr = ((const float4*)X) + (size_t)w * 128;
    const float4* vr = (const float4*)v;
    float s = 0.f;
#pragma unroll
    for (int i = 0; i < 4; i++) {
        float4 a = xr[lane + 32 * i];
        float4 b = __ldg(&vr[lane + 32 * i]);
        s += a.x * b.x + a.y * b.y + a.z * b.z + a.w * b.w;
    }
#pragma unroll
    for (int o = 16; o > 0; o >>= 1) s += __shfl_xor_sync(0xffffffffu, s, o);
    if (lane == 0) {
        if (mode == 1) out[w] = 1.f / (1.f + expf(-(s + bptr[0])));
        else out[w] = s;
    }
}

// ---------------- edge pass: ew=exp(tanh(ssc[s]+tsc[t]+cs+ct+ab)), den[s]+= ------
__global__ void edge_p1_kernel(const int* __restrict__ src, const int* __restrict__ tgt,
                               const float* __restrict__ ssc, const float* __restrict__ tsc,
                               const float* __restrict__ cs, const float* __restrict__ ct,
                               const float* __restrict__ abptr, int abidx,
                               float* __restrict__ ew, float* __restrict__ den, int E)
{
    int i = blockIdx.x * blockDim.x + threadIdx.x;
    if (i >= E) return;
    float e = tanhf(ssc[src[i]] + tsc[tgt[i]] + cs[0] + ct[0] + abptr[abidx]);
    float x = expf(e);
    ew[i] = x;
    atomicAdd(&den[src[i]], x);
}

// ---------------- scatter (warp per edge, float4 vector atomics) -----------
__global__ void scatter_kernel(const int* __restrict__ src, const int* __restrict__ tgt,
                               const float* __restrict__ ew, const float* __restrict__ den,
                               const float* __restrict__ t, float* __restrict__ hp, int E)
{
    int e = (blockIdx.x * blockDim.x + threadIdx.x) >> 5;
    int lane = threadIdx.x & 31;
    if (e >= E) return;
    int s = src[e], g = tgt[e];
    float alpha = ew[e] / den[s];
    const float4* tr = ((const float4*)t) + (size_t)g * 128;
    float4* hr = ((float4*)(hp + (size_t)s * 512));
#pragma unroll
    for (int i = 0; i < 4; i++) {
        float4 v = tr[lane + 32 * i];
        float4 w = make_float4(v.x * alpha, v.y * alpha, v.z * alpha, v.w * alpha);
        atomicAdd(hr + lane + 32 * i, w);
    }
}

// ------------- layernorm in place (mode1: v=tanh(x+x2) first) -------------
__global__ void ln_kernel(float* __restrict__ x, const float* __restrict__ x2,
                          const float* __restrict__ g, const float* __restrict__ b, int mode)
{
    int row = blockIdx.x;
    int tid = threadIdx.x;
    float4* xr = ((float4*)x) + (size_t)row * 128;
    float4 v = xr[tid];
    if (mode == 1) {
        float4 w = ((const float4*)x2)[(size_t)row * 128 + tid];
        v.x = tanhf(v.x + w.x); v.y = tanhf(v.y + w.y);
        v.z = tanhf(v.z + w.z); v.w = tanhf(v.w + w.w);
    }
    float sum = v.x + v.y + v.z + v.w;
    float sq  = v.x * v.x + v.y * v.y + v.z * v.z + v.w * v.w;
#pragma unroll
    for (int o = 16; o > 0; o >>= 1) {
        sum += __shfl_xor_sync(0xffffffffu, sum, o);
        sq  += __shfl_xor_sync(0xffffffffu, sq, o);
    }
    __shared__ float ssum[4], ssq[4], sstat[2];
    int wid = tid >> 5, lane = tid & 31;
    if (lane == 0) { ssum[wid] = sum; ssq[wid] = sq; }
    __syncthreads();
    if (tid == 0) {
        float ts = ssum[0] + ssum[1] + ssum[2] + ssum[3];
        float tq = ssq[0] + ssq[1] + ssq[2] + ssq[3];
        float mu = ts * (1.f / 512.f);
        float var = tq * (1.f / 512.f) - mu * mu;
        sstat[0] = mu;
        sstat[1] = rsqrtf(var + 1e-5f);
    }
    __syncthreads();
    float mu = sstat[0], rstd = sstat[1];
    float4 gg = __ldg(&((const float4*)g)[tid]);
    float4 bb = __ldg(&((const float4*)b)[tid]);
    v.x = (v.x - mu) * rstd * gg.x + bb.x;
    v.y = (v.y - mu) * rstd * gg.y + bb.y;
    v.z = (v.z - mu) * rstd * gg.z + bb.z;
    v.w = (v.w - mu) * rstd * gg.w + bb.w;
    xr[tid] = v;
}

// ---------------- zero (float4) ----------------
__global__ void zero_kernel(float* __restrict__ p, int n4)
{
    int i = blockIdx.x * blockDim.x + threadIdx.x;
    if (i < n4) ((float4*)p)[i] = make_float4(0.f, 0.f, 0.f, 0.f);
}

// =====================================================================================
extern "C" void kernel_launch(void* const* d_in, const int* in_sizes, int n_in,
                              void* d_out, int out_size)
{
    const int N = NN, H = HH, E = EE;

    const float* fu0 = (const float*)d_in[0];
    const float* fi1 = (const float*)d_in[3];
    const float* fu2 = (const float*)d_in[4];
    const int* eUI0 = (const int*)d_in[6];
    const int* eIU1 = (const int*)d_in[9];
    const float* Wu   = (const float*)d_in[10];
    const float* bu   = (const float*)d_in[11];
    const float* Wi   = (const float*)d_in[12];
    const float* bi   = (const float*)d_in[13];
    const float* gatW = (const float*)d_in[14];
    const float* gatb = (const float*)d_in[15];
    const float* aw   = (const float*)d_in[16];
    const float* ab   = (const float*)d_in[17];
    const float* gbias= (const float*)d_in[18];
    const float* prepW= (const float*)d_in[19];
    const float* prepb= (const float*)d_in[20];
    const float* dnnW = (const float*)d_in[21];
    const float* dnnb = (const float*)d_in[22];
    const float* lng  = (const float*)d_in[23];
    const float* lnb  = (const float*)d_in[24];
    const float* rlng = (const float*)d_in[25];
    const float* rlnb = (const float*)d_in[26];
    const float* clsW = (const float*)d_in[27];
    const float* clsb = (const float*)d_in[28];

    float *bufA, *bufB, *bufC, *bufD, *bufF, *bufG, *hp, *ssc, *tsc, *den, *ew, *ws, *wt;
    __nv_bfloat16 *bth0, *btl0, *bth1, *btl1;
    cudaGetSymbolAddress((void**)&bufA, g_bufA);
    cudaGetSymbolAddress((void**)&bufB, g_bufB);
    cudaGetSymbolAddress((void**)&bufC, g_bufC);
    cudaGetSymbolAddress((void**)&bufD, g_bufD);
    cudaGetSymbolAddress((void**)&bufF, g_bufF);
    cudaGetSymbolAddress((void**)&bufG, g_bufG);
    cudaGetSymbolAddress((void**)&hp,   g_hp);
    cudaGetSymbolAddress((void**)&ssc,  g_ssc);
    cudaGetSymbolAddress((void**)&tsc,  g_tsc);
    cudaGetSymbolAddress((void**)&den,  g_den);
    cudaGetSymbolAddress((void**)&ew,   g_ew);
    cudaGetSymbolAddress((void**)&ws,   g_ws);
    cudaGetSymbolAddress((void**)&wt,   g_wt);
    cudaGetSymbolAddress((void**)&bth0, g_bth0);
    cudaGetSymbolAddress((void**)&btl0, g_btl0);
    cudaGetSymbolAddress((void**)&bth1, g_bth1);
    cudaGetSymbolAddress((void**)&btl1, g_btl1);

    cudaFuncSetAttribute(tc_gemm, cudaFuncAttributeMaxDynamicSharedMemorySize, GEMM_SMEM);

    dim3 gemmGrid(4, (N + BM - 1) / BM);
    const int rowdotBlocks = (N * 32 + 255) / 256;
    const int edgeBlocks = (E + 255) / 256;
    const int scatBlocks = (E * 32 + 255) / 256;
    const int nh4 = N * (H / 4);
    const int zeroHPblocks = (nh4 + 255) / 256;
    const int zeroDenBlocks = ((N / 4) + 255) / 256;

    auto splitW = [&](const float* B, __nv_bfloat16* th, __nv_bfloat16* tl, int K) {
        splitT_kernel<<<(K * 512 + 255) / 256, 256>>>(B, th, tl, K, 512);
    };
    auto gemm = [&](const float* A, const __nv_bfloat16* th, const __nv_bfloat16* tl,
                    const float* bias, const float* h, const float* g, float* C,
                    int K, int op) {
        tc_gemm<<<gemmGrid, 256, GEMM_SMEM>>>(A, th, tl, bias, h, g, C, N, K, op);
    };

    // --- node transforms (dead-code-eliminated graph) ---
    splitW(Wu, bth0, btl0, 512);                 // pair0 = Wu (reused at hop 0)
    splitW(Wi, bth1, btl1, 256);
    gemm(fu2, bth0, btl0, bu, nullptr, nullptr, bufA, 512, 0);   // su_h2 (raw scatter payload)
    gemm(fi1, bth1, btl1, bi, nullptr, nullptr, bufB, 256, 0);   // hi_h1

    // --- GAT rel 1 @ hop 1: head=hi_h1, tail=su_h2, edges_IU_h1 ---
    const float* fW1 = gatW + (size_t)H * H;
    const float* fb1 = gatb + H;
    prepw_kernel<<<5, 128>>>(fW1, fb1, aw + 2 * H, ws);
    prepw_kernel<<<5, 128>>>(fW1, fb1, aw + 3 * H, wt);
    rowdot_kernel<<<rowdotBlocks, 256>>>(bufB, ws, nullptr, ssc, N, 0);
    rowdot_kernel<<<rowdotBlocks, 256>>>(bufA, wt, nullptr, tsc, N, 0);
    zero_kernel<<<zeroDenBlocks, 256>>>(den, N / 4);
    edge_p1_kernel<<<edgeBlocks, 256>>>(eIU1, eIU1 + E, ssc, tsc, ws + 512, wt + 512, ab, 1, ew, den, E);
    zero_kernel<<<zeroHPblocks, 256>>>(hp, nh4);
    scatter_kernel<<<scatBlocks, 256>>>(eIU1, eIU1 + E, ew, den, bufA, hp, E);   // agg raw su_h2
    splitW(fW1, bth1, btl1, 512);
    // si_new = (hi_h1 + (agg@fW1 + fb1) + gat_bias1) * 0.5   — fused combine epilogue
    gemm(hp, bth1, btl1, fb1, bufB, gbias + H, bufF, 512, 2);

    // --- GAT rel 0 @ hop 0: head=hu_h0, tail=si_new, edges_UI_h0 ---
    gemm(fu0, bth0, btl0, bu, nullptr, nullptr, bufG, 512, 0);   // hu_h0 (Wu pair reused)
    prepw_kernel<<<5, 128>>>(gatW, gatb, aw, ws);
    prepw_kernel<<<5, 128>>>(gatW, gatb, aw + H, wt);
    rowdot_kernel<<<rowdotBlocks, 256>>>(bufG, ws, nullptr, ssc, N, 0);
    rowdot_kernel<<<rowdotBlocks, 256>>>(bufF, wt, nullptr, tsc, N, 0);
    zero_kernel<<<zeroDenBlocks, 256>>>(den, N / 4);
    edge_p1_kernel<<<edgeBlocks, 256>>>(eUI0, eUI0 + E, ssc, tsc, ws + 512, wt + 512, ab, 0, ew, den, E);
    zero_kernel<<<zeroHPblocks, 256>>>(hp, nh4);
    scatter_kernel<<<scatBlocks, 256>>>(eUI0, eUI0 + E, ew, den, bufF, hp, E);   // agg raw si_new
    splitW(gatW, bth1, btl1, 512);
    // su_final = (hu_h0 + (agg@fW0 + fb0) + gat_bias0) * 0.5
    gemm(hp, bth1, btl1, gatb, bufG, gbias, bufA, 512, 2);

    // --- Res_DNN head ---
    splitW(prepW, bth0, btl0, 512);
    gemm(bufA, bth0, btl0, prepb, nullptr, nullptr, bufB, 512, 0);   // x
    for (int r = 0; r < 2; r++) {
        splitW(dnnW + (size_t)(r * 2 + 0) * H * H, bth0, btl0, 512);
        gemm(bufB, bth0, btl0, dnnb + (r * 2 + 0) * H, nullptr, nullptr, bufC, 512, 1);
        ln_kernel<<<N, 128>>>(bufC, nullptr, lng + (r * 2 + 0) * H, lnb + (r * 2 + 0) * H, 0);
        splitW(dnnW + (size_t)(r * 2 + 1) * H * H, bth0, btl0, 512);
        gemm(bufC, bth0, btl0, dnnb + (r * 2 + 1) * H, nullptr, nullptr, bufD, 512, 1);
        ln_kernel<<<N, 128>>>(bufD, nullptr, lng + (r * 2 + 1) * H, lnb + (r * 2 + 1) * H, 0);
        ln_kernel<<<N, 128>>>(bufB, bufD, rlng + r * H, rlnb + r * H, 1);   // x = LN(tanh(sc+x))
    }

    // --- classifier + sigmoid ---
    rowdot_kernel<<<rowdotBlocks, 256>>>(bufB, clsW, clsb, (float*)d_out, N, 1);
}

// round 11
// speedup vs baseline: 2.6972x; 1.0018x over previous
#include <cuda_runtime.h>
#include <cuda_bf16.h>
#include <math.h>
#include <stdint.h>

#define NN 20000
#define HH 512
#define EE 200000

// ---------------- scratch (static device globals; no allocation) ----------------
__device__ float g_bufA[NN * HH];
__device__ float g_bufB[NN * HH];
__device__ float g_bufC[NN * HH];
__device__ float g_bufD[NN * HH];
__device__ float g_bufF[NN * HH];
__device__ float g_bufG[NN * HH];
__device__ float g_hp[NN * HH];
__device__ float g_ssc[NN];
__device__ float g_tsc[NN];
__device__ float g_den[NN];
__device__ float g_ew[EE];
__device__ float g_ws0[513];
__device__ float g_wt0[513];
__device__ float g_ws1[513];
__device__ float g_wt1[513];
__device__ __nv_bfloat16 g_bth0[HH * HH];   // weight split pair 0 (hi)  [512 rows, K]
__device__ __nv_bfloat16 g_btl0[HH * HH];   // weight split pair 0 (lo)
__device__ __nv_bfloat16 g_bth1[HH * HH];   // weight split pair 1 (hi)
__device__ __nv_bfloat16 g_btl1[HH * HH];   // weight split pair 1 (lo)

// ======================= tensor-core GEMM (mma.sync bf16x3, fp32 A input) =======================
// C[M,512] = A[M,K] @ W[K,512] + bias.  A arrives fp32; split to bf16 hi/lo in-kernel.
// Block 128x128, BK=32, 8 warps (warp tile 64x32), cp.async double buffer, ldmatrix.
// op: 0 = bias; 1 = bias+tanh; 2 = fused combine: out = (h + acc + bias + gvec) * 0.5
// Optional fused per-row dot: dout[row] += sum_col out[row,col]*dvec[col] (atomic).

#define BM 128
#define BN 128
#define BK 32
#define PAD 40
#define AH_OFF 0
#define BH_OFF 10240
#define BL_OFF 20480
#define STG_OFF 30720                      // fp32 staging; reused as A-lo bf16 after convert
#define STAGE_BYTES 47104
#define GEMM_SMEM (2 * STAGE_BYTES)        // 94208 B -> occupancy 2

__device__ __forceinline__ void cp16(uint32_t saddr, const void* gptr) {
    asm volatile("cp.async.cg.shared.global [%0], [%1], 16;" :: "r"(saddr), "l"(gptr));
}
__device__ __forceinline__ void cp_commit() { asm volatile("cp.async.commit_group;"); }
template <int N> __device__ __forceinline__ void cp_wait() {
    asm volatile("cp.async.wait_group %0;" :: "n"(N));
}
__device__ __forceinline__ void ldsm4(uint32_t* r, uint32_t addr) {
    asm volatile("ldmatrix.sync.aligned.m8n8.x4.shared.b16 {%0,%1,%2,%3}, [%4];"
                 : "=r"(r[0]), "=r"(r[1]), "=r"(r[2]), "=r"(r[3]) : "r"(addr));
}
__device__ __forceinline__ void mma16816(float* c, const uint32_t* a, uint32_t b0, uint32_t b1) {
    asm volatile(
        "mma.sync.aligned.m16n8k16.row.col.f32.bf16.bf16.f32 "
        "{%0,%1,%2,%3}, {%4,%5,%6,%7}, {%8,%9}, {%0,%1,%2,%3};"
        : "+f"(c[0]), "+f"(c[1]), "+f"(c[2]), "+f"(c[3])
        : "r"(a[0]), "r"(a[1]), "r"(a[2]), "r"(a[3]), "r"(b0), "r"(b1));
}
__device__ __forceinline__ uint32_t pack_bf2(float a, float b) {
    __nv_bfloat162 h = __nv_bfloat162(__float2bfloat16(a), __float2bfloat16(b));
    return *(uint32_t*)&h;
}

__global__ __launch_bounds__(256, 2)
void tc_gemm(const float* __restrict__ A,
             const __nv_bfloat16* __restrict__ Bh, const __nv_bfloat16* __restrict__ Bl,
             const float* __restrict__ bias, const float* __restrict__ hsrc,
             const float* __restrict__ gvec, float* __restrict__ C,
             const float* __restrict__ dvec, float* __restrict__ dout,
             int M, int K, int op)
{
    extern __shared__ char sm[];
    const int tid = threadIdx.x;
    const int wid = tid >> 5;
    const int lane = tid & 31;
    const int rowBase = blockIdx.y * BM;
    const int colBase = blockIdx.x * BN;
    const int nChunks = K >> 5;

    const int m_base = (wid & 1) * 64;
    const int n_base = (wid >> 1) * 32;
    const uint32_t smemBase = (uint32_t)__cvta_generic_to_shared(sm);

    float acc[4][4][4];
#pragma unroll
    for (int mi = 0; mi < 4; mi++)
#pragma unroll
        for (int nj = 0; nj < 4; nj++)
#pragma unroll
            for (int r = 0; r < 4; r++) acc[mi][nj][r] = 0.f;

    // ---- stage loader: B (bf16 hi/lo) + A (fp32 staging), all cp.async ----
    auto loadStage = [&](int s, int k0) {
        uint32_t st = smemBase + s * STAGE_BYTES;
#pragma unroll
        for (int i = 0; i < 2; i++) {                 // B: 512 chunks x2 matrices
            int chunk = tid + i * 256;
            int r = chunk >> 2, seg = chunk & 3;
            uint32_t d = st + (uint32_t)(r * PAD + seg * 8) * 2;
            size_t boff = (size_t)(colBase + r) * K + k0 + seg * 8;
            cp16(d + BH_OFF, Bh + boff);
            cp16(d + BL_OFF, Bl + boff);
        }
#pragma unroll
        for (int i = 0; i < 4; i++) {                 // A fp32: 1024 chunks of 16B
            int chunk = tid + i * 256;
            int r = chunk >> 3, seg = chunk & 7;
            int grow = rowBase + r; if (grow > M - 1) grow = M - 1;
            cp16(st + STG_OFF + (uint32_t)(r * 128 + seg * 16),
                 A + (size_t)grow * K + k0 + seg * 4);
        }
    };

    // ---- convert own-loaded fp32 A chunks -> bf16 hi (AH) / lo (back into staging) ----
    auto convertA = [&](int s) {
        char* st = sm + s * STAGE_BYTES;
        uint32_t lo[4][2];
        uint32_t dst[4];
#pragma unroll
        for (int i = 0; i < 4; i++) {
            int chunk = tid + i * 256;
            int r = chunk >> 3, seg = chunk & 7;
            float4 v = *(const float4*)(st + STG_OFF + r * 128 + seg * 16);
            uint32_t hi0 = pack_bf2(v.x, v.y), hi1 = pack_bf2(v.z, v.w);
            __nv_bfloat162 h01 = *(__nv_bfloat162*)&hi0;
            __nv_bfloat162 h23 = *(__nv_bfloat162*)&hi1;
            lo[i][0] = pack_bf2(v.x - __bfloat162float(h01.x), v.y - __bfloat162float(h01.y));
            lo[i][1] = pack_bf2(v.z - __bfloat162float(h23.x), v.w - __bfloat162float(h23.y));
            uint32_t off = (uint32_t)(r * PAD + seg * 4) * 2;
            *(uint2*)(st + AH_OFF + off) = make_uint2(hi0, hi1);
            dst[i] = off;
        }
        __syncthreads();                 // all staging reads done before lo overwrites
#pragma unroll
        for (int i = 0; i < 4; i++)
            *(uint2*)(st + STG_OFF + dst[i]) = make_uint2(lo[i][0], lo[i][1]);
    };

    const int lr = lane & 7;
    const int lg = lane >> 3;
    const uint32_t aRowOff = (uint32_t)((lg & 1) * 8 + lr) * PAD + (uint32_t)(lg >> 1) * 8;

    loadStage(0, 0);
    cp_commit();

    for (int c = 0; c < nChunks; c++) {
        int s = c & 1;
        if (c + 1 < nChunks) { loadStage(s ^ 1, (c + 1) * BK); cp_commit(); cp_wait<1>(); }
        else cp_wait<0>();
        convertA(s);
        __syncthreads();                 // hi/lo + B visible to all warps

        uint32_t base = smemBase + s * STAGE_BYTES;
        uint32_t baseAh = base + AH_OFF;
        uint32_t baseAl = base + STG_OFF;
        uint32_t baseBh = base + BH_OFF;
        uint32_t baseBl = base + BL_OFF;

#pragma unroll
        for (int kk = 0; kk < BK; kk += 16) {
            uint32_t bh[4][2], bl[4][2];
#pragma unroll
            for (int p = 0; p < 2; p++) {
                uint32_t off = ((uint32_t)(n_base + p * 16 + (lg & 1) * 8 + lr) * PAD
                                + kk + (lg >> 1) * 8) * 2;
                uint32_t t[4];
                ldsm4(t, baseBh + off);
                bh[2 * p][0] = t[0]; bh[2 * p][1] = t[2];
                bh[2 * p + 1][0] = t[1]; bh[2 * p + 1][1] = t[3];
                ldsm4(t, baseBl + off);
                bl[2 * p][0] = t[0]; bl[2 * p][1] = t[2];
                bl[2 * p + 1][0] = t[1]; bl[2 * p + 1][1] = t[3];
            }
#pragma unroll
            for (int mi = 0; mi < 4; mi++) {
                uint32_t off = (aRowOff + (uint32_t)(m_base + mi * 16) * PAD + kk) * 2;
                uint32_t af[4], afl[4];
                ldsm4(af, baseAh + off);
                ldsm4(afl, baseAl + off);
#pragma unroll
                for (int nj = 0; nj < 4; nj++) {
                    mma16816(acc[mi][nj], af, bh[nj][0], bh[nj][1]);
                    mma16816(acc[mi][nj], af, bl[nj][0], bl[nj][1]);
                    mma16816(acc[mi][nj], afl, bh[nj][0], bh[nj][1]);
                }
            }
        }
        __syncthreads();                 // stage reuse barrier
    }

    // ---- epilogue (+ optional fused per-row dot) ----
#pragma unroll
    for (int mi = 0; mi < 4; mi++) {
        int row0 = rowBase + m_base + mi * 16 + (lane >> 2);
        int row1 = row0 + 8;
        float d0 = 0.f, d1 = 0.f;
#pragma unroll
        for (int nj = 0; nj < 4; nj++) {
            int col = colBase + n_base + nj * 8 + (lane & 3) * 2;
            float b0 = __ldg(bias + col), b1 = __ldg(bias + col + 1);
            float2 v0 = make_float2(acc[mi][nj][0] + b0, acc[mi][nj][1] + b1);
            float2 v1 = make_float2(acc[mi][nj][2] + b0, acc[mi][nj][3] + b1);
            if (op == 1) {
                v0.x = tanhf(v0.x); v0.y = tanhf(v0.y);
                v1.x = tanhf(v1.x); v1.y = tanhf(v1.y);
            } else if (op == 2) {
                float g0 = __ldg(gvec + col), g1 = __ldg(gvec + col + 1);
                if (row0 < M) {
                    float2 h = *(const float2*)(hsrc + (size_t)row0 * 512 + col);
                    v0.x = (h.x + v0.x + g0) * 0.5f;
                    v0.y = (h.y + v0.y + g1) * 0.5f;
                }
                if (row1 < M) {
                    float2 h = *(const float2*)(hsrc + (size_t)row1 * 512 + col);
                    v1.x = (h.x + v1.x + g0) * 0.5f;
                    v1.y = (h.y + v1.y + g1) * 0.5f;
                }
            }
            if (dout) {
                float w0 = __ldg(dvec + col), w1 = __ldg(dvec + col + 1);
                d0 += v0.x * w0 + v0.y * w1;
                d1 += v1.x * w0 + v1.y * w1;
            }
            if (row0 < M) *(float2*)(C + (size_t)row0 * 512 + col) = v0;
            if (row1 < M) *(float2*)(C + (size_t)row1 * 512 + col) = v1;
        }
        if (dout) {
            d0 += __shfl_xor_sync(0xffffffffu, d0, 1);
            d0 += __shfl_xor_sync(0xffffffffu, d0, 2);
            d1 += __shfl_xor_sync(0xffffffffu, d1, 1);
            d1 += __shfl_xor_sync(0xffffffffu, d1, 2);
            if ((lane & 3) == 0) {
                if (row0 < M) atomicAdd(dout + row0, d0);
                if (row1 < M) atomicAdd(dout + row1, d1);
            }
        }
    }
}

// ------------- transpose + split weights: B[K,N] fp32 -> Bt hi/lo [N,K] bf16 -------------
__global__ void splitT_kernel(const float* __restrict__ B, __nv_bfloat16* __restrict__ th,
                              __nv_bfloat16* __restrict__ tl, int K, int Ncols)
{
    int idx = blockIdx.x * blockDim.x + threadIdx.x;
    if (idx >= K * Ncols) return;
    int n = idx / K, k = idx - n * K;
    float x = B[(size_t)k * Ncols + n];
    __nv_bfloat16 hi = __float2bfloat16(x);
    th[idx] = hi;
    tl[idx] = __float2bfloat16(x - __bfloat162float(hi));
}

// -------- fold attention vector into feature weights: w'[k]=fW[k,:].aw; w'[512]=fb.aw --------
__global__ void prepw_kernel(const float* __restrict__ fW, const float* __restrict__ fb,
                             const float* __restrict__ aw, float* __restrict__ out)
{
    int k = blockIdx.x * blockDim.x + threadIdx.x;
    if (k > 512) return;
    const float* row = (k < 512) ? (fW + (size_t)k * 512) : fb;
    float s = 0.f;
    const float4* r4 = (const float4*)row;
    const float4* a4 = (const float4*)aw;
#pragma unroll 4
    for (int j = 0; j < 128; j++) {
        float4 a = __ldg(&r4[j]);
        float4 b = __ldg(&a4[j]);
        s += a.x * b.x + a.y * b.y + a.z * b.z + a.w * b.w;
    }
    out[k] = s;
}

// ---------------- edge pass: ew=exp(tanh(ssc[s]+tsc[t]+cs+ct+ab)), den[s]+= ------
__global__ void edge_p1_kernel(const int* __restrict__ src, const int* __restrict__ tgt,
                               const float* __restrict__ ssc, const float* __restrict__ tsc,
                               const float* __restrict__ cs, const float* __restrict__ ct,
                               const float* __restrict__ abptr, int abidx,
                               float* __restrict__ ew, float* __restrict__ den, int E)
{
    int i = blockIdx.x * blockDim.x + threadIdx.x;
    if (i >= E) return;
    float e = tanhf(ssc[src[i]] + tsc[tgt[i]] + cs[0] + ct[0] + abptr[abidx]);
    float x = expf(e);
    ew[i] = x;
    atomicAdd(&den[src[i]], x);
}

// ---------------- scatter (warp per edge, float4 vector atomics) -----------
__global__ void scatter_kernel(const int* __restrict__ src, const int* __restrict__ tgt,
                               const float* __restrict__ ew, const float* __restrict__ den,
                               const float* __restrict__ t, float* __restrict__ hp, int E)
{
    int e = (blockIdx.x * blockDim.x + threadIdx.x) >> 5;
    int lane = threadIdx.x & 31;
    if (e >= E) return;
    int s = src[e], g = tgt[e];
    float alpha = ew[e] / den[s];
    const float4* tr = ((const float4*)t) + (size_t)g * 128;
    float4* hr = ((float4*)(hp + (size_t)s * 512));
#pragma unroll
    for (int i = 0; i < 4; i++) {
        float4 v = tr[lane + 32 * i];
        float4 w = make_float4(v.x * alpha, v.y * alpha, v.z * alpha, v.w * alpha);
        atomicAdd(hr + lane + 32 * i, w);
    }
}

// ------------- layernorm in place (mode1: v=tanh(x+x2) first) -------------
// Optional fused classifier: if cls != nullptr, write sigmoid(LN(v).cls + cb) to douty
// and SKIP the 41MB store of the normalized row (dead afterwards).
__global__ void ln_kernel(float* __restrict__ x, const float* __restrict__ x2,
                          const float* __restrict__ g, const float* __restrict__ b,
                          const float* __restrict__ cls, const float* __restrict__ cb,
                          float* __restrict__ douty, int mode)
{
    int row = blockIdx.x;
    int tid = threadIdx.x;
    float4* xr = ((float4*)x) + (size_t)row * 128;
    float4 v = xr[tid];
    if (mode == 1) {
        float4 w = ((const float4*)x2)[(size_t)row * 128 + tid];
        v.x = tanhf(v.x + w.x); v.y = tanhf(v.y + w.y);
        v.z = tanhf(v.z + w.z); v.w = tanhf(v.w + w.w);
    }
    float sum = v.x + v.y + v.z + v.w;
    float sq  = v.x * v.x + v.y * v.y + v.z * v.z + v.w * v.w;
#pragma unroll
    for (int o = 16; o > 0; o >>= 1) {
        sum += __shfl_xor_sync(0xffffffffu, sum, o);
        sq  += __shfl_xor_sync(0xffffffffu, sq, o);
    }
    __shared__ float ssum[4], ssq[4], sstat[2], sdot[4];
    int wid = tid >> 5, lane = tid & 31;
    if (lane == 0) { ssum[wid] = sum; ssq[wid] = sq; }
    __syncthreads();
    if (tid == 0) {
        float ts = ssum[0] + ssum[1] + ssum[2] + ssum[3];
        float tq = ssq[0] + ssq[1] + ssq[2] + ssq[3];
        float mu = ts * (1.f / 512.f);
        float var = tq * (1.f / 512.f) - mu * mu;
        sstat[0] = mu;
        sstat[1] = rsqrtf(var + 1e-5f);
    }
    __syncthreads();
    float mu = sstat[0], rstd = sstat[1];
    float4 gg = __ldg(&((const float4*)g)[tid]);
    float4 bb = __ldg(&((const float4*)b)[tid]);
    v.x = (v.x - mu) * rstd * gg.x + bb.x;
    v.y = (v.y - mu) * rstd * gg.y + bb.y;
    v.z = (v.z - mu) * rstd * gg.z + bb.z;
    v.w = (v.w - mu) * rstd * gg.w + bb.w;
    if (cls == nullptr) {
        xr[tid] = v;
    } else {
        float4 c = __ldg(&((const float4*)cls)[tid]);
        float p = v.x * c.x + v.y * c.y + v.z * c.z + v.w * c.w;
#pragma unroll
        for (int o = 16; o > 0; o >>= 1) p += __shfl_xor_sync(0xffffffffu, p, o);
        if (lane == 0) sdot[wid] = p;
        __syncthreads();
        if (tid == 0) {
            float tot = sdot[0] + sdot[1] + sdot[2] + sdot[3] + cb[0];
            douty[row] = 1.f / (1.f + expf(-tot));
        }
    }
}

// ---------------- zero (float4) ----------------
__global__ void zero_kernel(float* __restrict__ p, int n4)
{
    int i = blockIdx.x * blockDim.x + threadIdx.x;
    if (i < n4) ((float4*)p)[i] = make_float4(0.f, 0.f, 0.f, 0.f);
}

// =====================================================================================
extern "C" void kernel_launch(void* const* d_in, const int* in_sizes, int n_in,
                              void* d_out, int out_size)
{
    const int N = NN, H = HH, E = EE;

    const float* fu0 = (const float*)d_in[0];
    const float* fi1 = (const float*)d_in[3];
    const float* fu2 = (const float*)d_in[4];
    const int* eUI0 = (const int*)d_in[6];
    const int* eIU1 = (const int*)d_in[9];
    const float* Wu   = (const float*)d_in[10];
    const float* bu   = (const float*)d_in[11];
    const float* Wi   = (const float*)d_in[12];
    const float* bi   = (const float*)d_in[13];
    const float* gatW = (const float*)d_in[14];
    const float* gatb = (const float*)d_in[15];
    const float* aw   = (const float*)d_in[16];
    const float* ab   = (const float*)d_in[17];
    const float* gbias= (const float*)d_in[18];
    const float* prepW= (const float*)d_in[19];
    const float* prepb= (const float*)d_in[20];
    const float* dnnW = (const float*)d_in[21];
    const float* dnnb = (const float*)d_in[22];
    const float* lng  = (const float*)d_in[23];
    const float* lnb  = (const float*)d_in[24];
    const float* rlng = (const float*)d_in[25];
    const float* rlnb = (const float*)d_in[26];
    const float* clsW = (const float*)d_in[27];
    const float* clsb = (const float*)d_in[28];

    float *bufA, *bufB, *bufC, *bufD, *bufF, *bufG, *hp, *ssc, *tsc, *den, *ew;
    float *ws0, *wt0, *ws1, *wt1;
    __nv_bfloat16 *bth0, *btl0, *bth1, *btl1;
    cudaGetSymbolAddress((void**)&bufA, g_bufA);
    cudaGetSymbolAddress((void**)&bufB, g_bufB);
    cudaGetSymbolAddress((void**)&bufC, g_bufC);
    cudaGetSymbolAddress((void**)&bufD, g_bufD);
    cudaGetSymbolAddress((void**)&bufF, g_bufF);
    cudaGetSymbolAddress((void**)&bufG, g_bufG);
    cudaGetSymbolAddress((void**)&hp,   g_hp);
    cudaGetSymbolAddress((void**)&ssc,  g_ssc);
    cudaGetSymbolAddress((void**)&tsc,  g_tsc);
    cudaGetSymbolAddress((void**)&den,  g_den);
    cudaGetSymbolAddress((void**)&ew,   g_ew);
    cudaGetSymbolAddress((void**)&ws0,  g_ws0);
    cudaGetSymbolAddress((void**)&wt0,  g_wt0);
    cudaGetSymbolAddress((void**)&ws1,  g_ws1);
    cudaGetSymbolAddress((void**)&wt1,  g_wt1);
    cudaGetSymbolAddress((void**)&bth0, g_bth0);
    cudaGetSymbolAddress((void**)&btl0, g_btl0);
    cudaGetSymbolAddress((void**)&bth1, g_bth1);
    cudaGetSymbolAddress((void**)&btl1, g_btl1);

    cudaFuncSetAttribute(tc_gemm, cudaFuncAttributeMaxDynamicSharedMemorySize, GEMM_SMEM);

    dim3 gemmGrid(4, (N + BM - 1) / BM);
    const int edgeBlocks = (E + 255) / 256;
    const int scatBlocks = (E * 32 + 255) / 256;
    const int nh4 = N * (H / 4);
    const int zeroHPblocks = (nh4 + 255) / 256;
    const int zeroNblocks = ((N / 4) + 255) / 256;

    auto splitW = [&](const float* B, __nv_bfloat16* th, __nv_bfloat16* tl, int K) {
        splitT_kernel<<<(K * 512 + 255) / 256, 256>>>(B, th, tl, K, 512);
    };
    auto gemm = [&](const float* A, const __nv_bfloat16* th, const __nv_bfloat16* tl,
                    const float* bias, const float* h, const float* g, float* C,
                    const float* dvec, float* dout, int K, int op) {
        tc_gemm<<<gemmGrid, 256, GEMM_SMEM>>>(A, th, tl, bias, h, g, C, dvec, dout, N, K, op);
    };
    auto zeroN = [&](float* p) { zero_kernel<<<zeroNblocks, 256>>>(p, N / 4); };

    // --- folded attention vectors (all independent of node data; hoisted) ---
    const float* fW1 = gatW + (size_t)H * H;
    const float* fb1 = gatb + H;
    prepw_kernel<<<5, 128>>>(fW1, fb1, aw + 2 * H, ws1);
    prepw_kernel<<<5, 128>>>(fW1, fb1, aw + 3 * H, wt1);
    prepw_kernel<<<5, 128>>>(gatW, gatb, aw, ws0);
    prepw_kernel<<<5, 128>>>(gatW, gatb, aw + H, wt0);

    // --- node transforms with fused attention dots ---
    splitW(Wu, bth0, btl0, 512);                 // pair0 = Wu (reused at hop 0)
    splitW(Wi, bth1, btl1, 256);
    zeroN(ssc); zeroN(tsc);
    gemm(fu2, bth0, btl0, bu, nullptr, nullptr, bufA, wt1, tsc, 512, 0);  // su_h2 (+dot wt1)
    gemm(fi1, bth1, btl1, bi, nullptr, nullptr, bufB, ws1, ssc, 256, 0);  // hi_h1 (+dot ws1)

    // --- GAT rel 1 @ hop 1: head=hi_h1, tail=su_h2, edges_IU_h1 ---
    zeroN(den);
    edge_p1_kernel<<<edgeBlocks, 256>>>(eIU1, eIU1 + E, ssc, tsc, ws1 + 512, wt1 + 512, ab, 1, ew, den, E);
    zero_kernel<<<zeroHPblocks, 256>>>(hp, nh4);
    scatter_kernel<<<scatBlocks, 256>>>(eIU1, eIU1 + E, ew, den, bufA, hp, E);   // agg raw su_h2
    splitW(fW1, bth1, btl1, 512);
    zeroN(ssc); zeroN(tsc);
    // si_new = (hi_h1 + (agg@fW1 + fb1) + gat_bias1) * 0.5  (+dot wt0 -> tsc for hop 0)
    gemm(hp, bth1, btl1, fb1, bufB, gbias + H, bufF, wt0, tsc, 512, 2);

    // --- GAT rel 0 @ hop 0: head=hu_h0, tail=si_new, edges_UI_h0 ---
    gemm(fu0, bth0, btl0, bu, nullptr, nullptr, bufG, ws0, ssc, 512, 0);  // hu_h0 (+dot ws0)
    zeroN(den);
    edge_p1_kernel<<<edgeBlocks, 256>>>(eUI0, eUI0 + E, ssc, tsc, ws0 + 512, wt0 + 512, ab, 0, ew, den, E);
    zero_kernel<<<zeroHPblocks, 256>>>(hp, nh4);
    scatter_kernel<<<scatBlocks, 256>>>(eUI0, eUI0 + E, ew, den, bufF, hp, E);   // agg raw si_new
    splitW(gatW, bth1, btl1, 512);
    // su_final = (hu_h0 + (agg@fW0 + fb0) + gat_bias0) * 0.5
    gemm(hp, bth1, btl1, gatb, bufG, gbias, bufA, nullptr, nullptr, 512, 2);

    // --- Res_DNN head ---
    splitW(prepW, bth0, btl0, 512);
    gemm(bufA, bth0, btl0, prepb, nullptr, nullptr, bufB, nullptr, nullptr, 512, 0);  // x
    for (int r = 0; r < 2; r++) {
        splitW(dnnW + (size_t)(r * 2 + 0) * H * H, bth0, btl0, 512);
        gemm(bufB, bth0, btl0, dnnb + (r * 2 + 0) * H, nullptr, nullptr, bufC, nullptr, nullptr, 512, 1);
        ln_kernel<<<N, 128>>>(bufC, nullptr, lng + (r * 2 + 0) * H, lnb + (r * 2 + 0) * H,
                              nullptr, nullptr, nullptr, 0);
        splitW(dnnW + (size_t)(r * 2 + 1) * H * H, bth0, btl0, 512);
        gemm(bufC, bth0, btl0, dnnb + (r * 2 + 1) * H, nullptr, nullptr, bufD, nullptr, nullptr, 512, 1);
        ln_kernel<<<N, 128>>>(bufD, nullptr, lng + (r * 2 + 1) * H, lnb + (r * 2 + 1) * H,
                              nullptr, nullptr, nullptr, 0);
        // x = LN(tanh(sc + x)); last residual LN fuses classifier dot + sigmoid -> d_out
        if (r == 0) {
            ln_kernel<<<N, 128>>>(bufB, bufD, rlng + r * H, rlnb + r * H,
                                  nullptr, nullptr, nullptr, 1);
        } else {
            ln_kernel<<<N, 128>>>(bufB, bufD, rlng + r * H, rlnb + r * H,
                                  clsW, clsb, (float*)d_out, 1);
        }
    }
}

// round 12
// speedup vs baseline: 2.8100x; 1.0418x over previous
#include <cuda_runtime.h>
#include <cuda_bf16.h>
#include <math.h>
#include <stdint.h>

#define NN 20000
#define HH 512
#define EE 200000

// ---------------- scratch (static device globals; no allocation) ----------------
__device__ float g_bufA[NN * HH];
__device__ float g_bufB[NN * HH];
__device__ float g_bufC[NN * HH];
__device__ float g_bufD[NN * HH];
__device__ float g_bufF[NN * HH];
__device__ float g_bufG[NN * HH];
__device__ float g_hp[NN * HH];
__device__ float g_ssc[NN];
__device__ float g_tsc[NN];
__device__ float g_den[NN];
__device__ float g_ew[EE];
__device__ float g_ws0[513];
__device__ float g_wt0[513];
__device__ float g_ws1[513];
__device__ float g_wt1[513];
__device__ __nv_bfloat16 g_bth0[HH * HH];   // weight split pair 0 (hi)  [512 rows, K]
__device__ __nv_bfloat16 g_btl0[HH * HH];   // weight split pair 0 (lo)
__device__ __nv_bfloat16 g_bth1[HH * HH];   // weight split pair 1 (hi)
__device__ __nv_bfloat16 g_btl1[HH * HH];   // weight split pair 1 (lo)

// ======================= tensor-core GEMM (mma.sync bf16x3, fp32 A input) =======================
// C[M,512] = A[M,K] @ W[K,512] + bias.  A arrives fp32; split to bf16 hi/lo in-kernel.
// Block 128x128, BK=32, 8 warps (warp tile 64x32), cp.async double buffer, ldmatrix.
// op: 0 = bias; 1 = bias+tanh; 2 = fused combine: out = (h + acc + bias + gvec) * 0.5
// Optional fused per-row dot: dout[row] += sum_col out[row,col]*dvec[col] (atomic).

#define BM 128
#define BN 128
#define BK 32
#define PAD 40
#define AH_OFF 0
#define BH_OFF 10240
#define BL_OFF 20480
#define STG_OFF 30720                      // fp32 staging; reused as A-lo bf16 after convert
#define STAGE_BYTES 47104
#define GEMM_SMEM (2 * STAGE_BYTES)        // 94208 B -> occupancy 2

__device__ __forceinline__ void cp16(uint32_t saddr, const void* gptr) {
    asm volatile("cp.async.cg.shared.global [%0], [%1], 16;" :: "r"(saddr), "l"(gptr));
}
__device__ __forceinline__ void cp_commit() { asm volatile("cp.async.commit_group;"); }
template <int N> __device__ __forceinline__ void cp_wait() {
    asm volatile("cp.async.wait_group %0;" :: "n"(N));
}
__device__ __forceinline__ void ldsm4(uint32_t* r, uint32_t addr) {
    asm volatile("ldmatrix.sync.aligned.m8n8.x4.shared.b16 {%0,%1,%2,%3}, [%4];"
                 : "=r"(r[0]), "=r"(r[1]), "=r"(r[2]), "=r"(r[3]) : "r"(addr));
}
__device__ __forceinline__ void mma16816(float* c, const uint32_t* a, uint32_t b0, uint32_t b1) {
    asm volatile(
        "mma.sync.aligned.m16n8k16.row.col.f32.bf16.bf16.f32 "
        "{%0,%1,%2,%3}, {%4,%5,%6,%7}, {%8,%9}, {%0,%1,%2,%3};"
        : "+f"(c[0]), "+f"(c[1]), "+f"(c[2]), "+f"(c[3])
        : "r"(a[0]), "r"(a[1]), "r"(a[2]), "r"(a[3]), "r"(b0), "r"(b1));
}
__device__ __forceinline__ uint32_t pack_bf2(float a, float b) {
    __nv_bfloat162 h = __nv_bfloat162(__float2bfloat16(a), __float2bfloat16(b));
    return *(uint32_t*)&h;
}

__global__ __launch_bounds__(256, 2)
void tc_gemm(const float* __restrict__ A,
             const __nv_bfloat16* __restrict__ Bh, const __nv_bfloat16* __restrict__ Bl,
             const float* __restrict__ bias, const float* __restrict__ hsrc,
             const float* __restrict__ gvec, float* __restrict__ C,
             const float* __restrict__ dvec, float* __restrict__ dout,
             int M, int K, int op)
{
    extern __shared__ char sm[];
    const int tid = threadIdx.x;
    const int wid = tid >> 5;
    const int lane = tid & 31;
    const int rowBase = blockIdx.y * BM;
    const int colBase = blockIdx.x * BN;
    const int nChunks = K >> 5;

    const int m_base = (wid & 1) * 64;
    const int n_base = (wid >> 1) * 32;
    const uint32_t smemBase = (uint32_t)__cvta_generic_to_shared(sm);

    float acc[4][4][4];
#pragma unroll
    for (int mi = 0; mi < 4; mi++)
#pragma unroll
        for (int nj = 0; nj < 4; nj++)
#pragma unroll
            for (int r = 0; r < 4; r++) acc[mi][nj][r] = 0.f;

    // ---- stage loader: B (bf16 hi/lo) + A (fp32 staging), all cp.async ----
    auto loadStage = [&](int s, int k0) {
        uint32_t st = smemBase + s * STAGE_BYTES;
#pragma unroll
        for (int i = 0; i < 2; i++) {                 // B: 512 chunks x2 matrices
            int chunk = tid + i * 256;
            int r = chunk >> 2, seg = chunk & 3;
            uint32_t d = st + (uint32_t)(r * PAD + seg * 8) * 2;
            size_t boff = (size_t)(colBase + r) * K + k0 + seg * 8;
            cp16(d + BH_OFF, Bh + boff);
            cp16(d + BL_OFF, Bl + boff);
        }
#pragma unroll
        for (int i = 0; i < 4; i++) {                 // A fp32: 1024 chunks of 16B
            int chunk = tid + i * 256;
            int r = chunk >> 3, seg = chunk & 7;
            int grow = rowBase + r; if (grow > M - 1) grow = M - 1;
            cp16(st + STG_OFF + (uint32_t)(r * 128 + seg * 16),
                 A + (size_t)grow * K + k0 + seg * 4);
        }
    };

    // ---- convert own-loaded fp32 A chunks -> bf16 hi (AH) / lo (back into staging) ----
    auto convertA = [&](int s) {
        char* st = sm + s * STAGE_BYTES;
        uint32_t lo[4][2];
        uint32_t dst[4];
#pragma unroll
        for (int i = 0; i < 4; i++) {
            int chunk = tid + i * 256;
            int r = chunk >> 3, seg = chunk & 7;
            float4 v = *(const float4*)(st + STG_OFF + r * 128 + seg * 16);
            uint32_t hi0 = pack_bf2(v.x, v.y), hi1 = pack_bf2(v.z, v.w);
            __nv_bfloat162 h01 = *(__nv_bfloat162*)&hi0;
            __nv_bfloat162 h23 = *(__nv_bfloat162*)&hi1;
            lo[i][0] = pack_bf2(v.x - __bfloat162float(h01.x), v.y - __bfloat162float(h01.y));
            lo[i][1] = pack_bf2(v.z - __bfloat162float(h23.x), v.w - __bfloat162float(h23.y));
            uint32_t off = (uint32_t)(r * PAD + seg * 4) * 2;
            *(uint2*)(st + AH_OFF + off) = make_uint2(hi0, hi1);
            dst[i] = off;
        }
        __syncthreads();                 // all staging reads done before lo overwrites
#pragma unroll
        for (int i = 0; i < 4; i++)
            *(uint2*)(st + STG_OFF + dst[i]) = make_uint2(lo[i][0], lo[i][1]);
    };

    const int lr = lane & 7;
    const int lg = lane >> 3;
    const uint32_t aRowOff = (uint32_t)((lg & 1) * 8 + lr) * PAD + (uint32_t)(lg >> 1) * 8;

    loadStage(0, 0);
    cp_commit();

    for (int c = 0; c < nChunks; c++) {
        int s = c & 1;
        if (c + 1 < nChunks) { loadStage(s ^ 1, (c + 1) * BK); cp_commit(); cp_wait<1>(); }
        else cp_wait<0>();
        convertA(s);
        __syncthreads();                 // hi/lo + B visible to all warps

        uint32_t base = smemBase + s * STAGE_BYTES;
        uint32_t baseAh = base + AH_OFF;
        uint32_t baseAl = base + STG_OFF;
        uint32_t baseBh = base + BH_OFF;
        uint32_t baseBl = base + BL_OFF;

#pragma unroll
        for (int kk = 0; kk < BK; kk += 16) {
            uint32_t bh[4][2], bl[4][2];
#pragma unroll
            for (int p = 0; p < 2; p++) {
                uint32_t off = ((uint32_t)(n_base + p * 16 + (lg & 1) * 8 + lr) * PAD
                                + kk + (lg >> 1) * 8) * 2;
                uint32_t t[4];
                ldsm4(t, baseBh + off);
                bh[2 * p][0] = t[0]; bh[2 * p][1] = t[2];
                bh[2 * p + 1][0] = t[1]; bh[2 * p + 1][1] = t[3];
                ldsm4(t, baseBl + off);
                bl[2 * p][0] = t[0]; bl[2 * p][1] = t[2];
                bl[2 * p + 1][0] = t[1]; bl[2 * p + 1][1] = t[3];
            }
#pragma unroll
            for (int mi = 0; mi < 4; mi++) {
                uint32_t off = (aRowOff + (uint32_t)(m_base + mi * 16) * PAD + kk) * 2;
                uint32_t af[4], afl[4];
                ldsm4(af, baseAh + off);
                ldsm4(afl, baseAl + off);
#pragma unroll
                for (int nj = 0; nj < 4; nj++) {
                    mma16816(acc[mi][nj], af, bh[nj][0], bh[nj][1]);
                    mma16816(acc[mi][nj], af, bl[nj][0], bl[nj][1]);
                    mma16816(acc[mi][nj], afl, bh[nj][0], bh[nj][1]);
                }
            }
        }
        __syncthreads();                 // stage reuse barrier
    }

    // ---- epilogue (+ optional fused per-row dot) ----
#pragma unroll
    for (int mi = 0; mi < 4; mi++) {
        int row0 = rowBase + m_base + mi * 16 + (lane >> 2);
        int row1 = row0 + 8;
        float d0 = 0.f, d1 = 0.f;
#pragma unroll
        for (int nj = 0; nj < 4; nj++) {
            int col = colBase + n_base + nj * 8 + (lane & 3) * 2;
            float b0 = __ldg(bias + col), b1 = __ldg(bias + col + 1);
            float2 v0 = make_float2(acc[mi][nj][0] + b0, acc[mi][nj][1] + b1);
            float2 v1 = make_float2(acc[mi][nj][2] + b0, acc[mi][nj][3] + b1);
            if (op == 1) {
                v0.x = tanhf(v0.x); v0.y = tanhf(v0.y);
                v1.x = tanhf(v1.x); v1.y = tanhf(v1.y);
            } else if (op == 2) {
                float g0 = __ldg(gvec + col), g1 = __ldg(gvec + col + 1);
                if (row0 < M) {
                    float2 h = *(const float2*)(hsrc + (size_t)row0 * 512 + col);
                    v0.x = (h.x + v0.x + g0) * 0.5f;
                    v0.y = (h.y + v0.y + g1) * 0.5f;
                }
                if (row1 < M) {
                    float2 h = *(const float2*)(hsrc + (size_t)row1 * 512 + col);
                    v1.x = (h.x + v1.x + g0) * 0.5f;
                    v1.y = (h.y + v1.y + g1) * 0.5f;
                }
            }
            if (dout) {
                float w0 = __ldg(dvec + col), w1 = __ldg(dvec + col + 1);
                d0 += v0.x * w0 + v0.y * w1;
                d1 += v1.x * w0 + v1.y * w1;
            }
            if (row0 < M) *(float2*)(C + (size_t)row0 * 512 + col) = v0;
            if (row1 < M) *(float2*)(C + (size_t)row1 * 512 + col) = v1;
        }
        if (dout) {
            d0 += __shfl_xor_sync(0xffffffffu, d0, 1);
            d0 += __shfl_xor_sync(0xffffffffu, d0, 2);
            d1 += __shfl_xor_sync(0xffffffffu, d1, 1);
            d1 += __shfl_xor_sync(0xffffffffu, d1, 2);
            if ((lane & 3) == 0) {
                if (row0 < M) atomicAdd(dout + row0, d0);
                if (row1 < M) atomicAdd(dout + row1, d1);
            }
        }
    }
}

// ------------- transpose + split weights: B[K,N] fp32 -> Bt hi/lo [N,K] bf16 -------------
__global__ void splitT_kernel(const float* __restrict__ B, __nv_bfloat16* __restrict__ th,
                              __nv_bfloat16* __restrict__ tl, int K, int Ncols)
{
    int idx = blockIdx.x * blockDim.x + threadIdx.x;
    if (idx >= K * Ncols) return;
    int n = idx / K, k = idx - n * K;
    float x = B[(size_t)k * Ncols + n];
    __nv_bfloat16 hi = __float2bfloat16(x);
    th[idx] = hi;
    tl[idx] = __float2bfloat16(x - __bfloat162float(hi));
}

// -------- fold all 4 attention vectors in ONE launch: warp per output element --------
// v=0: ws1 = fW1.aw[2H:3H]; v=1: wt1 = fW1.aw[3H:4H]; v=2: ws0 = fW0.aw[0:H]; v=3: wt0 = fW0.aw[H:2H]
// element k<512: dot(fW row k, awseg); k==512: dot(fb, awseg).
__global__ void prepw4_kernel(const float* __restrict__ gatW, const float* __restrict__ gatb,
                              const float* __restrict__ aw,
                              float* __restrict__ ws1, float* __restrict__ wt1,
                              float* __restrict__ ws0, float* __restrict__ wt0)
{
    int gw = (blockIdx.x * blockDim.x + threadIdx.x) >> 5;   // global warp id
    int lane = threadIdx.x & 31;
    if (gw >= 4 * 513) return;
    int v = gw / 513;
    int k = gw - v * 513;
    int rel = (v < 2) ? 1 : 0;
    int awseg = (v == 0) ? 2 : (v == 1) ? 3 : (v == 2) ? 0 : 1;
    const float* row = (k < 512) ? (gatW + (size_t)rel * HH * HH + (size_t)k * HH)
                                 : (gatb + rel * HH);
    const float4* r4 = (const float4*)row;
    const float4* a4 = (const float4*)(aw + awseg * HH);
    float s = 0.f;
#pragma unroll
    for (int j = 0; j < 4; j++) {
        float4 a = __ldg(&r4[lane + 32 * j]);
        float4 b = __ldg(&a4[lane + 32 * j]);
        s += a.x * b.x + a.y * b.y + a.z * b.z + a.w * b.w;
    }
#pragma unroll
    for (int o = 16; o > 0; o >>= 1) s += __shfl_xor_sync(0xffffffffu, s, o);
    if (lane == 0) {
        float* out = (v == 0) ? ws1 : (v == 1) ? wt1 : (v == 2) ? ws0 : wt0;
        out[k] = s;
    }
}

// ---------------- edge pass: ew=exp(tanh(ssc[s]+tsc[t]+cs+ct+ab)), den[s]+= ------
__global__ void edge_p1_kernel(const int* __restrict__ src, const int* __restrict__ tgt,
                               const float* __restrict__ ssc, const float* __restrict__ tsc,
                               const float* __restrict__ cs, const float* __restrict__ ct,
                               const float* __restrict__ abptr, int abidx,
                               float* __restrict__ ew, float* __restrict__ den, int E)
{
    int i = blockIdx.x * blockDim.x + threadIdx.x;
    if (i >= E) return;
    float e = tanhf(ssc[src[i]] + tsc[tgt[i]] + cs[0] + ct[0] + abptr[abidx]);
    float x = expf(e);
    ew[i] = x;
    atomicAdd(&den[src[i]], x);
}

// ---------------- scatter (warp per edge, float4 vector atomics) -----------
__global__ void scatter_kernel(const int* __restrict__ src, const int* __restrict__ tgt,
                               const float* __restrict__ ew, const float* __restrict__ den,
                               const float* __restrict__ t, float* __restrict__ hp, int E)
{
    int e = (blockIdx.x * blockDim.x + threadIdx.x) >> 5;
    int lane = threadIdx.x & 31;
    if (e >= E) return;
    int s = src[e], g = tgt[e];
    float alpha = ew[e] / den[s];
    const float4* tr = ((const float4*)t) + (size_t)g * 128;
    float4* hr = ((float4*)(hp + (size_t)s * 512));
#pragma unroll
    for (int i = 0; i < 4; i++) {
        float4 v = tr[lane + 32 * i];
        float4 w = make_float4(v.x * alpha, v.y * alpha, v.z * alpha, v.w * alpha);
        atomicAdd(hr + lane + 32 * i, w);
    }
}

// ------------- layernorm in place (mode1: v=tanh(x+x2) first) -------------
// Optional fused classifier: if cls != nullptr, write sigmoid(LN(v).cls + cb) to douty
// and SKIP the 41MB store of the normalized row (dead afterwards).
__global__ void ln_kernel(float* __restrict__ x, const float* __restrict__ x2,
                          const float* __restrict__ g, const float* __restrict__ b,
                          const float* __restrict__ cls, const float* __restrict__ cb,
                          float* __restrict__ douty, int mode)
{
    int row = blockIdx.x;
    int tid = threadIdx.x;
    float4* xr = ((float4*)x) + (size_t)row * 128;
    float4 v = xr[tid];
    if (mode == 1) {
        float4 w = ((const float4*)x2)[(size_t)row * 128 + tid];
        v.x = tanhf(v.x + w.x); v.y = tanhf(v.y + w.y);
        v.z = tanhf(v.z + w.z); v.w = tanhf(v.w + w.w);
    }
    float sum = v.x + v.y + v.z + v.w;
    float sq  = v.x * v.x + v.y * v.y + v.z * v.z + v.w * v.w;
#pragma unroll
    for (int o = 16; o > 0; o >>= 1) {
        sum += __shfl_xor_sync(0xffffffffu, sum, o);
        sq  += __shfl_xor_sync(0xffffffffu, sq, o);
    }
    __shared__ float ssum[4], ssq[4], sstat[2], sdot[4];
    int wid = tid >> 5, lane = tid & 31;
    if (lane == 0) { ssum[wid] = sum; ssq[wid] = sq; }
    __syncthreads();
    if (tid == 0) {
        float ts = ssum[0] + ssum[1] + ssum[2] + ssum[3];
        float tq = ssq[0] + ssq[1] + ssq[2] + ssq[3];
        float mu = ts * (1.f / 512.f);
        float var = tq * (1.f / 512.f) - mu * mu;
        sstat[0] = mu;
        sstat[1] = rsqrtf(var + 1e-5f);
    }
    __syncthreads();
    float mu = sstat[0], rstd = sstat[1];
    float4 gg = __ldg(&((const float4*)g)[tid]);
    float4 bb = __ldg(&((const float4*)b)[tid]);
    v.x = (v.x - mu) * rstd * gg.x + bb.x;
    v.y = (v.y - mu) * rstd * gg.y + bb.y;
    v.z = (v.z - mu) * rstd * gg.z + bb.z;
    v.w = (v.w - mu) * rstd * gg.w + bb.w;
    if (cls == nullptr) {
        xr[tid] = v;
    } else {
        float4 c = __ldg(&((const float4*)cls)[tid]);
        float p = v.x * c.x + v.y * c.y + v.z * c.z + v.w * c.w;
#pragma unroll
        for (int o = 16; o > 0; o >>= 1) p += __shfl_xor_sync(0xffffffffu, p, o);
        if (lane == 0) sdot[wid] = p;
        __syncthreads();
        if (tid == 0) {
            float tot = sdot[0] + sdot[1] + sdot[2] + sdot[3] + cb[0];
            douty[row] = 1.f / (1.f + expf(-tot));
        }
    }
}

// ---------------- zero (float4) ----------------
__global__ void zero_kernel(float* __restrict__ p, int n4)
{
    int i = blockIdx.x * blockDim.x + threadIdx.x;
    if (i < n4) ((float4*)p)[i] = make_float4(0.f, 0.f, 0.f, 0.f);
}

// =====================================================================================
extern "C" void kernel_launch(void* const* d_in, const int* in_sizes, int n_in,
                              void* d_out, int out_size)
{
    const int N = NN, H = HH, E = EE;

    const float* fu0 = (const float*)d_in[0];
    const float* fi1 = (const float*)d_in[3];
    const float* fu2 = (const float*)d_in[4];
    const int* eUI0 = (const int*)d_in[6];
    const int* eIU1 = (const int*)d_in[9];
    const float* Wu   = (const float*)d_in[10];
    const float* bu   = (const float*)d_in[11];
    const float* Wi   = (const float*)d_in[12];
    const float* bi   = (const float*)d_in[13];
    const float* gatW = (const float*)d_in[14];
    const float* gatb = (const float*)d_in[15];
    const float* aw   = (const float*)d_in[16];
    const float* ab   = (const float*)d_in[17];
    const float* gbias= (const float*)d_in[18];
    const float* prepW= (const float*)d_in[19];
    const float* prepb= (const float*)d_in[20];
    const float* dnnW = (const float*)d_in[21];
    const float* dnnb = (const float*)d_in[22];
    const float* lng  = (const float*)d_in[23];
    const float* lnb  = (const float*)d_in[24];
    const float* rlng = (const float*)d_in[25];
    const float* rlnb = (const float*)d_in[26];
    const float* clsW = (const float*)d_in[27];
    const float* clsb = (const float*)d_in[28];

    float *bufA, *bufB, *bufC, *bufD, *bufF, *bufG, *hp, *ssc, *tsc, *den, *ew;
    float *ws0, *wt0, *ws1, *wt1;
    __nv_bfloat16 *bth0, *btl0, *bth1, *btl1;
    cudaGetSymbolAddress((void**)&bufA, g_bufA);
    cudaGetSymbolAddress((void**)&bufB, g_bufB);
    cudaGetSymbolAddress((void**)&bufC, g_bufC);
    cudaGetSymbolAddress((void**)&bufD, g_bufD);
    cudaGetSymbolAddress((void**)&bufF, g_bufF);
    cudaGetSymbolAddress((void**)&bufG, g_bufG);
    cudaGetSymbolAddress((void**)&hp,   g_hp);
    cudaGetSymbolAddress((void**)&ssc,  g_ssc);
    cudaGetSymbolAddress((void**)&tsc,  g_tsc);
    cudaGetSymbolAddress((void**)&den,  g_den);
    cudaGetSymbolAddress((void**)&ew,   g_ew);
    cudaGetSymbolAddress((void**)&ws0,  g_ws0);
    cudaGetSymbolAddress((void**)&wt0,  g_wt0);
    cudaGetSymbolAddress((void**)&ws1,  g_ws1);
    cudaGetSymbolAddress((void**)&wt1,  g_wt1);
    cudaGetSymbolAddress((void**)&bth0, g_bth0);
    cudaGetSymbolAddress((void**)&btl0, g_btl0);
    cudaGetSymbolAddress((void**)&bth1, g_bth1);
    cudaGetSymbolAddress((void**)&btl1, g_btl1);

    cudaFuncSetAttribute(tc_gemm, cudaFuncAttributeMaxDynamicSharedMemorySize, GEMM_SMEM);

    dim3 gemmGrid(4, (N + BM - 1) / BM);
    const int edgeBlocks = (E + 255) / 256;
    const int scatBlocks = (E * 32 + 255) / 256;
    const int nh4 = N * (H / 4);
    const int zeroHPblocks = (nh4 + 255) / 256;
    const int zeroNblocks = ((N / 4) + 255) / 256;

    auto splitW = [&](const float* B, __nv_bfloat16* th, __nv_bfloat16* tl, int K) {
        splitT_kernel<<<(K * 512 + 255) / 256, 256>>>(B, th, tl, K, 512);
    };
    auto gemm = [&](const float* A, const __nv_bfloat16* th, const __nv_bfloat16* tl,
                    const float* bias, const float* h, const float* g, float* C,
                    const float* dvec, float* dout, int K, int op) {
        tc_gemm<<<gemmGrid, 256, GEMM_SMEM>>>(A, th, tl, bias, h, g, C, dvec, dout, N, K, op);
    };
    auto zeroN = [&](float* p) { zero_kernel<<<zeroNblocks, 256>>>(p, N / 4); };

    // --- all 4 folded attention vectors in ONE full-chip launch ---
    prepw4_kernel<<<(4 * 513 * 32 + 255) / 256, 256>>>(gatW, gatb, aw, ws1, wt1, ws0, wt0);

    // --- node transforms with fused attention dots ---
    splitW(Wu, bth0, btl0, 512);                 // pair0 = Wu (reused at hop 0)
    splitW(Wi, bth1, btl1, 256);
    zeroN(ssc); zeroN(tsc);
    gemm(fu2, bth0, btl0, bu, nullptr, nullptr, bufA, wt1, tsc, 512, 0);  // su_h2 (+dot wt1)
    gemm(fi1, bth1, btl1, bi, nullptr, nullptr, bufB, ws1, ssc, 256, 0);  // hi_h1 (+dot ws1)

    // --- GAT rel 1 @ hop 1: head=hi_h1, tail=su_h2, edges_IU_h1 ---
    const float* fW1 = gatW + (size_t)H * H;
    const float* fb1 = gatb + H;
    zeroN(den);
    edge_p1_kernel<<<edgeBlocks, 256>>>(eIU1, eIU1 + E, ssc, tsc, ws1 + 512, wt1 + 512, ab, 1, ew, den, E);
    zero_kernel<<<zeroHPblocks, 256>>>(hp, nh4);
    scatter_kernel<<<scatBlocks, 256>>>(eIU1, eIU1 + E, ew, den, bufA, hp, E);   // agg raw su_h2
    splitW(fW1, bth1, btl1, 512);
    zeroN(ssc); zeroN(tsc);
    // si_new = (hi_h1 + (agg@fW1 + fb1) + gat_bias1) * 0.5  (+dot wt0 -> tsc for hop 0)
    gemm(hp, bth1, btl1, fb1, bufB, gbias + H, bufF, wt0, tsc, 512, 2);

    // --- GAT rel 0 @ hop 0: head=hu_h0, tail=si_new, edges_UI_h0 ---
    gemm(fu0, bth0, btl0, bu, nullptr, nullptr, bufG, ws0, ssc, 512, 0);  // hu_h0 (+dot ws0)
    zeroN(den);
    edge_p1_kernel<<<edgeBlocks, 256>>>(eUI0, eUI0 + E, ssc, tsc, ws0 + 512, wt0 + 512, ab, 0, ew, den, E);
    zero_kernel<<<zeroHPblocks, 256>>>(hp, nh4);
    scatter_kernel<<<scatBlocks, 256>>>(eUI0, eUI0 + E, ew, den, bufF, hp, E);   // agg raw si_new
    splitW(gatW, bth1, btl1, 512);
    // su_final = (hu_h0 + (agg@fW0 + fb0) + gat_bias0) * 0.5
    gemm(hp, bth1, btl1, gatb, bufG, gbias, bufA, nullptr, nullptr, 512, 2);

    // --- Res_DNN head ---
    splitW(prepW, bth0, btl0, 512);
    gemm(bufA, bth0, btl0, prepb, nullptr, nullptr, bufB, nullptr, nullptr, 512, 0);  // x
    for (int r = 0; r < 2; r++) {
        splitW(dnnW + (size_t)(r * 2 + 0) * H * H, bth0, btl0, 512);
        gemm(bufB, bth0, btl0, dnnb + (r * 2 + 0) * H, nullptr, nullptr, bufC, nullptr, nullptr, 512, 1);
        ln_kernel<<<N, 128>>>(bufC, nullptr, lng + (r * 2 + 0) * H, lnb + (r * 2 + 0) * H,
                              nullptr, nullptr, nullptr, 0);
        splitW(dnnW + (size_t)(r * 2 + 1) * H * H, bth0, btl0, 512);
        gemm(bufC, bth0, btl0, dnnb + (r * 2 + 1) * H, nullptr, nullptr, bufD, nullptr, nullptr, 512, 1);
        ln_kernel<<<N, 128>>>(bufD, nullptr, lng + (r * 2 + 1) * H, lnb + (r * 2 + 1) * H,
                              nullptr, nullptr, nullptr, 0);
        // x = LN(tanh(sc + x)); last residual LN fuses classifier dot + sigmoid -> d_out
        if (r == 0) {
            ln_kernel<<<N, 128>>>(bufB, bufD, rlng + r * H, rlnb + r * H,
                                  nullptr, nullptr, nullptr, 1);
        } else {
            ln_kernel<<<N, 128>>>(bufB, bufD, rlng + r * H, rlnb + r * H,
                                  clsW, clsb, (float*)d_out, 1);
        }
    }
}

// round 16
// speedup vs baseline: 2.8412x; 1.0111x over previous
#include <cuda_runtime.h>
#include <cuda_bf16.h>
#include <math.h>
#include <stdint.h>

#define NN 20000
#define HH 512
#define EE 200000

// ---------------- scratch (static device globals; no allocation) ----------------
__device__ float g_bufA[NN * HH];
__device__ float g_bufB[NN * HH];
__device__ float g_bufC[NN * HH];
__device__ float g_bufD[NN * HH];
__device__ float g_bufF[NN * HH];
__device__ float g_bufG[NN * HH];
__device__ float g_hp[NN * HH];
__device__ float g_ssc[NN];
__device__ float g_tsc[NN];
__device__ float g_ws0[513];
__device__ float g_wt0[513];
__device__ float g_ws1[513];
__device__ float g_wt1[513];
__device__ int g_cnt[NN];
__device__ int g_cursor[NN];
__device__ int g_rowptr0[NN + 1];
__device__ int g_rowptr1[NN + 1];
__device__ int g_csr0[EE];
__device__ int g_csr1[EE];
__device__ __nv_bfloat16 g_bth0[HH * HH];   // weight split pair 0 (hi)  [512 rows, K]
__device__ __nv_bfloat16 g_btl0[HH * HH];   // weight split pair 0 (lo)
__device__ __nv_bfloat16 g_bth1[HH * HH];   // weight split pair 1 (hi)
__device__ __nv_bfloat16 g_btl1[HH * HH];   // weight split pair 1 (lo)

// ======================= tensor-core GEMM (mma.sync bf16x3, fp32 A input) =======================
#define BM 128
#define BN 128
#define BK 32
#define PAD 40
#define AH_OFF 0
#define BH_OFF 10240
#define BL_OFF 20480
#define STG_OFF 30720
#define STAGE_BYTES 47104
#define GEMM_SMEM (2 * STAGE_BYTES)

__device__ __forceinline__ void cp16(uint32_t saddr, const void* gptr) {
    asm volatile("cp.async.cg.shared.global [%0], [%1], 16;" :: "r"(saddr), "l"(gptr));
}
__device__ __forceinline__ void cp_commit() { asm volatile("cp.async.commit_group;"); }
template <int N> __device__ __forceinline__ void cp_wait() {
    asm volatile("cp.async.wait_group %0;" :: "n"(N));
}
__device__ __forceinline__ void ldsm4(uint32_t* r, uint32_t addr) {
    asm volatile("ldmatrix.sync.aligned.m8n8.x4.shared.b16 {%0,%1,%2,%3}, [%4];"
                 : "=r"(r[0]), "=r"(r[1]), "=r"(r[2]), "=r"(r[3]) : "r"(addr));
}
__device__ __forceinline__ void mma16816(float* c, const uint32_t* a, uint32_t b0, uint32_t b1) {
    asm volatile(
        "mma.sync.aligned.m16n8k16.row.col.f32.bf16.bf16.f32 "
        "{%0,%1,%2,%3}, {%4,%5,%6,%7}, {%8,%9}, {%0,%1,%2,%3};"
        : "+f"(c[0]), "+f"(c[1]), "+f"(c[2]), "+f"(c[3])
        : "r"(a[0]), "r"(a[1]), "r"(a[2]), "r"(a[3]), "r"(b0), "r"(b1));
}
__device__ __forceinline__ uint32_t pack_bf2(float a, float b) {
    __nv_bfloat162 h = __nv_bfloat162(__float2bfloat16(a), __float2bfloat16(b));
    return *(uint32_t*)&h;
}

__global__ __launch_bounds__(256, 2)
void tc_gemm(const float* __restrict__ A,
             const __nv_bfloat16* __restrict__ Bh, const __nv_bfloat16* __restrict__ Bl,
             const float* __restrict__ bias, const float* __restrict__ hsrc,
             const float* __restrict__ gvec, float* __restrict__ C,
             const float* __restrict__ dvec, float* __restrict__ dout,
             int M, int K, int op)
{
    extern __shared__ char sm[];
    const int tid = threadIdx.x;
    const int wid = tid >> 5;
    const int lane = tid & 31;
    const int rowBase = blockIdx.y * BM;
    const int colBase = blockIdx.x * BN;
    const int nChunks = K >> 5;

    const int m_base = (wid & 1) * 64;
    const int n_base = (wid >> 1) * 32;
    const uint32_t smemBase = (uint32_t)__cvta_generic_to_shared(sm);

    float acc[4][4][4];
#pragma unroll
    for (int mi = 0; mi < 4; mi++)
#pragma unroll
        for (int nj = 0; nj < 4; nj++)
#pragma unroll
            for (int r = 0; r < 4; r++) acc[mi][nj][r] = 0.f;

    auto loadStage = [&](int s, int k0) {
        uint32_t st = smemBase + s * STAGE_BYTES;
#pragma unroll
        for (int i = 0; i < 2; i++) {
            int chunk = tid + i * 256;
            int r = chunk >> 2, seg = chunk & 3;
            uint32_t d = st + (uint32_t)(r * PAD + seg * 8) * 2;
            size_t boff = (size_t)(colBase + r) * K + k0 + seg * 8;
            cp16(d + BH_OFF, Bh + boff);
            cp16(d + BL_OFF, Bl + boff);
        }
#pragma unroll
        for (int i = 0; i < 4; i++) {
            int chunk = tid + i * 256;
            int r = chunk >> 3, seg = chunk & 7;
            int grow = rowBase + r; if (grow > M - 1) grow = M - 1;
            cp16(st + STG_OFF + (uint32_t)(r * 128 + seg * 16),
                 A + (size_t)grow * K + k0 + seg * 4);
        }
    };

    auto convertA = [&](int s) {
        char* st = sm + s * STAGE_BYTES;
        uint32_t lo[4][2];
        uint32_t dst[4];
#pragma unroll
        for (int i = 0; i < 4; i++) {
            int chunk = tid + i * 256;
            int r = chunk >> 3, seg = chunk & 7;
            float4 v = *(const float4*)(st + STG_OFF + r * 128 + seg * 16);
            uint32_t hi0 = pack_bf2(v.x, v.y), hi1 = pack_bf2(v.z, v.w);
            __nv_bfloat162 h01 = *(__nv_bfloat162*)&hi0;
            __nv_bfloat162 h23 = *(__nv_bfloat162*)&hi1;
            lo[i][0] = pack_bf2(v.x - __bfloat162float(h01.x), v.y - __bfloat162float(h01.y));
            lo[i][1] = pack_bf2(v.z - __bfloat162float(h23.x), v.w - __bfloat162float(h23.y));
            uint32_t off = (uint32_t)(r * PAD + seg * 4) * 2;
            *(uint2*)(st + AH_OFF + off) = make_uint2(hi0, hi1);
            dst[i] = off;
        }
        __syncthreads();
#pragma unroll
        for (int i = 0; i < 4; i++)
            *(uint2*)(st + STG_OFF + dst[i]) = make_uint2(lo[i][0], lo[i][1]);
    };

    const int lr = lane & 7;
    const int lg = lane >> 3;
    const uint32_t aRowOff = (uint32_t)((lg & 1) * 8 + lr) * PAD + (uint32_t)(lg >> 1) * 8;

    loadStage(0, 0);
    cp_commit();

    for (int c = 0; c < nChunks; c++) {
        int s = c & 1;
        if (c + 1 < nChunks) { loadStage(s ^ 1, (c + 1) * BK); cp_commit(); cp_wait<1>(); }
        else cp_wait<0>();
        convertA(s);
        __syncthreads();

        uint32_t base = smemBase + s * STAGE_BYTES;
        uint32_t baseAh = base + AH_OFF;
        uint32_t baseAl = base + STG_OFF;
        uint32_t baseBh = base + BH_OFF;
        uint32_t baseBl = base + BL_OFF;

#pragma unroll
        for (int kk = 0; kk < BK; kk += 16) {
            uint32_t bh[4][2], bl[4][2];
#pragma unroll
            for (int p = 0; p < 2; p++) {
                uint32_t off = ((uint32_t)(n_base + p * 16 + (lg & 1) * 8 + lr) * PAD
                                + kk + (lg >> 1) * 8) * 2;
                uint32_t t[4];
                ldsm4(t, baseBh + off);
                bh[2 * p][0] = t[0]; bh[2 * p][1] = t[2];
                bh[2 * p + 1][0] = t[1]; bh[2 * p + 1][1] = t[3];
                ldsm4(t, baseBl + off);
                bl[2 * p][0] = t[0]; bl[2 * p][1] = t[2];
                bl[2 * p + 1][0] = t[1]; bl[2 * p + 1][1] = t[3];
            }
#pragma unroll
            for (int mi = 0; mi < 4; mi++) {
                uint32_t off = (aRowOff + (uint32_t)(m_base + mi * 16) * PAD + kk) * 2;
                uint32_t af[4], afl[4];
                ldsm4(af, baseAh + off);
                ldsm4(afl, baseAl + off);
#pragma unroll
                for (int nj = 0; nj < 4; nj++) {
                    mma16816(acc[mi][nj], af, bh[nj][0], bh[nj][1]);
                    mma16816(acc[mi][nj], af, bl[nj][0], bl[nj][1]);
                    mma16816(acc[mi][nj], afl, bh[nj][0], bh[nj][1]);
                }
            }
        }
        __syncthreads();
    }

    // ---- epilogue (+ optional fused per-row dot) ----
#pragma unroll
    for (int mi = 0; mi < 4; mi++) {
        int row0 = rowBase + m_base + mi * 16 + (lane >> 2);
        int row1 = row0 + 8;
        float d0 = 0.f, d1 = 0.f;
#pragma unroll
        for (int nj = 0; nj < 4; nj++) {
            int col = colBase + n_base + nj * 8 + (lane & 3) * 2;
            float b0 = __ldg(bias + col), b1 = __ldg(bias + col + 1);
            float2 v0 = make_float2(acc[mi][nj][0] + b0, acc[mi][nj][1] + b1);
            float2 v1 = make_float2(acc[mi][nj][2] + b0, acc[mi][nj][3] + b1);
            if (op == 1) {
                v0.x = tanhf(v0.x); v0.y = tanhf(v0.y);
                v1.x = tanhf(v1.x); v1.y = tanhf(v1.y);
            } else if (op == 2) {
                float g0 = __ldg(gvec + col), g1 = __ldg(gvec + col + 1);
                if (row0 < M) {
                    float2 h = *(const float2*)(hsrc + (size_t)row0 * 512 + col);
                    v0.x = (h.x + v0.x + g0) * 0.5f;
                    v0.y = (h.y + v0.y + g1) * 0.5f;
                }
                if (row1 < M) {
                    float2 h = *(const float2*)(hsrc + (size_t)row1 * 512 + col);
                    v1.x = (h.x + v1.x + g0) * 0.5f;
                    v1.y = (h.y + v1.y + g1) * 0.5f;
                }
            }
            if (dout) {
                float w0 = __ldg(dvec + col), w1 = __ldg(dvec + col + 1);
                d0 += v0.x * w0 + v0.y * w1;
                d1 += v1.x * w0 + v1.y * w1;
            }
            if (row0 < M) *(float2*)(C + (size_t)row0 * 512 + col) = v0;
            if (row1 < M) *(float2*)(C + (size_t)row1 * 512 + col) = v1;
        }
        if (dout) {
            d0 += __shfl_xor_sync(0xffffffffu, d0, 1);
            d0 += __shfl_xor_sync(0xffffffffu, d0, 2);
            d1 += __shfl_xor_sync(0xffffffffu, d1, 1);
            d1 += __shfl_xor_sync(0xffffffffu, d1, 2);
            if ((lane & 3) == 0) {
                if (row0 < M) atomicAdd(dout + row0, d0);
                if (row1 < M) atomicAdd(dout + row1, d1);
            }
        }
    }
}

// ------------- transpose + split weights: B[K,N] fp32 -> Bt hi/lo [N,K] bf16 -------------
__global__ void splitT_kernel(const float* __restrict__ B, __nv_bfloat16* __restrict__ th,
                              __nv_bfloat16* __restrict__ tl, int K, int Ncols)
{
    int idx = blockIdx.x * blockDim.x + threadIdx.x;
    if (idx >= K * Ncols) return;
    int n = idx / K, k = idx - n * K;
    float x = B[(size_t)k * Ncols + n];
    __nv_bfloat16 hi = __float2bfloat16(x);
    th[idx] = hi;
    tl[idx] = __float2bfloat16(x - __bfloat162float(hi));
}

// -------- fold all 4 attention vectors in ONE launch: warp per output element --------
__global__ void prepw4_kernel(const float* __restrict__ gatW, const float* __restrict__ gatb,
                              const float* __restrict__ aw,
                              float* __restrict__ ws1, float* __restrict__ wt1,
                              float* __restrict__ ws0, float* __restrict__ wt0)
{
    int gw = (blockIdx.x * blockDim.x + threadIdx.x) >> 5;
    int lane = threadIdx.x & 31;
    if (gw >= 4 * 513) return;
    int v = gw / 513;
    int k = gw - v * 513;
    int rel = (v < 2) ? 1 : 0;
    int awseg = (v == 0) ? 2 : (v == 1) ? 3 : (v == 2) ? 0 : 1;
    const float* row = (k < 512) ? (gatW + (size_t)rel * HH * HH + (size_t)k * HH)
                                 : (gatb + rel * HH);
    const float4* r4 = (const float4*)row;
    const float4* a4 = (const float4*)(aw + awseg * HH);
    float s = 0.f;
#pragma unroll
    for (int j = 0; j < 4; j++) {
        float4 a = __ldg(&r4[lane + 32 * j]);
        float4 b = __ldg(&a4[lane + 32 * j]);
        s += a.x * b.x + a.y * b.y + a.z * b.z + a.w * b.w;
    }
#pragma unroll
    for (int o = 16; o > 0; o >>= 1) s += __shfl_xor_sync(0xffffffffu, s, o);
    if (lane == 0) {
        float* out = (v == 0) ? ws1 : (v == 1) ? wt1 : (v == 2) ? ws0 : wt0;
        out[k] = s;
    }
}

// ---------------- CSR build: histogram / scan / reorder ----------------
__global__ void hist_kernel(const int* __restrict__ src, int* __restrict__ cnt, int E)
{
    int i = blockIdx.x * blockDim.x + threadIdx.x;
    if (i < E) atomicAdd(&cnt[src[i]], 1);
}

__global__ __launch_bounds__(512) void scan_kernel(const int* __restrict__ cnt,
                                                   int* __restrict__ rowptr,
                                                   int* __restrict__ cursor, int n)
{
    __shared__ int part[512];
    int tid = threadIdx.x;
    int per = (n + 511) / 512;
    int start = tid * per;
    int local = 0;
    for (int j = 0; j < per; j++)
        if (start + j < n) local += cnt[start + j];
    part[tid] = local;
    __syncthreads();
    for (int off = 1; off < 512; off <<= 1) {
        int v = part[tid];
        int add = (tid >= off) ? part[tid - off] : 0;
        __syncthreads();
        part[tid] = v + add;
        __syncthreads();
    }
    int run = (tid > 0) ? part[tid - 1] : 0;
    for (int j = 0; j < per; j++) {
        int idx = start + j;
        if (idx < n) {
            rowptr[idx] = run;
            cursor[idx] = run;
            run += cnt[idx];
        }
    }
    if (tid == 511) rowptr[n] = part[511];
}

__global__ void reorder_kernel(const int* __restrict__ src, const int* __restrict__ tgt,
                               int* __restrict__ cursor, int* __restrict__ csr, int E)
{
    int i = blockIdx.x * blockDim.x + threadIdx.x;
    if (i >= E) return;
    int pos = atomicAdd(&cursor[src[i]], 1);
    csr[pos] = tgt[i];
}

// ---------------- CSR gather: warp per src row, softmax-weighted sum ----------------
// hp[s,:] = sum_e alpha_e * t[tgt_e,:];  alpha = exp(tanh(ssc[s]+tsc[tgt]+c)) / den.
__global__ __launch_bounds__(256) void gather_kernel(
    const int* __restrict__ rowptr, const int* __restrict__ csr,
    const float* __restrict__ ssc, const float* __restrict__ tsc,
    const float* __restrict__ cs, const float* __restrict__ ct,
    const float* __restrict__ abptr, int abidx,
    const float* __restrict__ t, float* __restrict__ hp, int n)
{
    int w = (blockIdx.x * blockDim.x + threadIdx.x) >> 5;
    int lane = threadIdx.x & 31;
    if (w >= n) return;
    int beg = rowptr[w], end = rowptr[w + 1];
    float4* out = (float4*)(hp + (size_t)w * 512);
    if (beg == end) {
        float4 z = make_float4(0.f, 0.f, 0.f, 0.f);
#pragma unroll
        for (int j = 0; j < 4; j++) out[lane + 32 * j] = z;
        return;
    }
    float base = ssc[w] + cs[0] + ct[0] + abptr[abidx];
    float den = 0.f;
    for (int i = beg + lane; i < end; i += 32)
        den += expf(tanhf(base + tsc[csr[i]]));
#pragma unroll
    for (int o = 16; o > 0; o >>= 1) den += __shfl_xor_sync(0xffffffffu, den, o);
    float inv = 1.f / den;
    float4 acc[4];
#pragma unroll
    for (int j = 0; j < 4; j++) acc[j] = make_float4(0.f, 0.f, 0.f, 0.f);
    for (int i = beg; i < end; i++) {
        int g = csr[i];
        float alpha = expf(tanhf(base + tsc[g])) * inv;
        const float4* tr = ((const float4*)t) + (size_t)g * 128;
#pragma unroll
        for (int j = 0; j < 4; j++) {
            float4 v = tr[lane + 32 * j];
            acc[j].x += alpha * v.x; acc[j].y += alpha * v.y;
            acc[j].z += alpha * v.z; acc[j].w += alpha * v.w;
        }
    }
#pragma unroll
    for (int j = 0; j < 4; j++) out[lane + 32 * j] = acc[j];
}

// ------------- layernorm in place (mode1: v=tanh(x+x2) first) -------------
__global__ void ln_kernel(float* __restrict__ x, const float* __restrict__ x2,
                          const float* __restrict__ g, const float* __restrict__ b,
                          const float* __restrict__ cls, const float* __restrict__ cb,
                          float* __restrict__ douty, int mode)
{
    int row = blockIdx.x;
    int tid = threadIdx.x;
    float4* xr = ((float4*)x) + (size_t)row * 128;
    float4 v = xr[tid];
    if (mode == 1) {
        float4 w = ((const float4*)x2)[(size_t)row * 128 + tid];
        v.x = tanhf(v.x + w.x); v.y = tanhf(v.y + w.y);
        v.z = tanhf(v.z + w.z); v.w = tanhf(v.w + w.w);
    }
    float sum = v.x + v.y + v.z + v.w;
    float sq  = v.x * v.x + v.y * v.y + v.z * v.z + v.w * v.w;
#pragma unroll
    for (int o = 16; o > 0; o >>= 1) {
        sum += __shfl_xor_sync(0xffffffffu, sum, o);
        sq  += __shfl_xor_sync(0xffffffffu, sq, o);
    }
    __shared__ float ssum[4], ssq[4], sstat[2], sdot[4];
    int wid = tid >> 5, lane = tid & 31;
    if (lane == 0) { ssum[wid] = sum; ssq[wid] = sq; }
    __syncthreads();
    if (tid == 0) {
        float ts = ssum[0] + ssum[1] + ssum[2] + ssum[3];
        float tq = ssq[0] + ssq[1] + ssq[2] + ssq[3];
        float mu = ts * (1.f / 512.f);
        float var = tq * (1.f / 512.f) - mu * mu;
        sstat[0] = mu;
        sstat[1] = rsqrtf(var + 1e-5f);
    }
    __syncthreads();
    float mu = sstat[0], rstd = sstat[1];
    float4 gg = __ldg(&((const float4*)g)[tid]);
    float4 bb = __ldg(&((const float4*)b)[tid]);
    v.x = (v.x - mu) * rstd * gg.x + bb.x;
    v.y = (v.y - mu) * rstd * gg.y + bb.y;
    v.z = (v.z - mu) * rstd * gg.z + bb.z;
    v.w = (v.w - mu) * rstd * gg.w + bb.w;
    if (cls == nullptr) {
        xr[tid] = v;
    } else {
        float4 c = __ldg(&((const float4*)cls)[tid]);
        float p = v.x * c.x + v.y * c.y + v.z * c.z + v.w * c.w;
#pragma unroll
        for (int o = 16; o > 0; o >>= 1) p += __shfl_xor_sync(0xffffffffu, p, o);
        if (lane == 0) sdot[wid] = p;
        __syncthreads();
        if (tid == 0) {
            float tot = sdot[0] + sdot[1] + sdot[2] + sdot[3] + cb[0];
            douty[row] = 1.f / (1.f + expf(-tot));
        }
    }
}

// ---------------- zero (float4) ----------------
__global__ void zero_kernel(float* __restrict__ p, int n4)
{
    int i = blockIdx.x * blockDim.x + threadIdx.x;
    if (i < n4) ((float4*)p)[i] = make_float4(0.f, 0.f, 0.f, 0.f);
}

// =====================================================================================
extern "C" void kernel_launch(void* const* d_in, const int* in_sizes, int n_in,
                              void* d_out, int out_size)
{
    const int N = NN, H = HH, E = EE;

    const float* fu0 = (const float*)d_in[0];
    const float* fi1 = (const float*)d_in[3];
    const float* fu2 = (const float*)d_in[4];
    const int* eUI0 = (const int*)d_in[6];
    const int* eIU1 = (const int*)d_in[9];
    const float* Wu   = (const float*)d_in[10];
    const float* bu   = (const float*)d_in[11];
    const float* Wi   = (const float*)d_in[12];
    const float* bi   = (const float*)d_in[13];
    const float* gatW = (const float*)d_in[14];
    const float* gatb = (const float*)d_in[15];
    const float* aw   = (const float*)d_in[16];
    const float* ab   = (const float*)d_in[17];
    const float* gbias= (const float*)d_in[18];
    const float* prepW= (const float*)d_in[19];
    const float* prepb= (const float*)d_in[20];
    const float* dnnW = (const float*)d_in[21];
    const float* dnnb = (const float*)d_in[22];
    const float* lng  = (const float*)d_in[23];
    const float* lnb  = (const float*)d_in[24];
    const float* rlng = (const float*)d_in[25];
    const float* rlnb = (const float*)d_in[26];
    const float* clsW = (const float*)d_in[27];
    const float* clsb = (const float*)d_in[28];

    float *bufA, *bufB, *bufC, *bufD, *bufF, *bufG, *hp, *ssc, *tsc;
    float *ws0, *wt0, *ws1, *wt1;
    int *cnt, *cursor, *rowptr0, *rowptr1, *csr0, *csr1;
    __nv_bfloat16 *bth0, *btl0, *bth1, *btl1;
    cudaGetSymbolAddress((void**)&bufA, g_bufA);
    cudaGetSymbolAddress((void**)&bufB, g_bufB);
    cudaGetSymbolAddress((void**)&bufC, g_bufC);
    cudaGetSymbolAddress((void**)&bufD, g_bufD);
    cudaGetSymbolAddress((void**)&bufF, g_bufF);
    cudaGetSymbolAddress((void**)&bufG, g_bufG);
    cudaGetSymbolAddress((void**)&hp,   g_hp);
    cudaGetSymbolAddress((void**)&ssc,  g_ssc);
    cudaGetSymbolAddress((void**)&tsc,  g_tsc);
    cudaGetSymbolAddress((void**)&ws0,  g_ws0);
    cudaGetSymbolAddress((void**)&wt0,  g_wt0);
    cudaGetSymbolAddress((void**)&ws1,  g_ws1);
    cudaGetSymbolAddress((void**)&wt1,  g_wt1);
    cudaGetSymbolAddress((void**)&cnt,     g_cnt);
    cudaGetSymbolAddress((void**)&cursor,  g_cursor);
    cudaGetSymbolAddress((void**)&rowptr0, g_rowptr0);
    cudaGetSymbolAddress((void**)&rowptr1, g_rowptr1);
    cudaGetSymbolAddress((void**)&csr0,    g_csr0);
    cudaGetSymbolAddress((void**)&csr1,    g_csr1);
    cudaGetSymbolAddress((void**)&bth0, g_bth0);
    cudaGetSymbolAddress((void**)&btl0, g_btl0);
    cudaGetSymbolAddress((void**)&bth1, g_bth1);
    cudaGetSymbolAddress((void**)&btl1, g_btl1);

    cudaFuncSetAttribute(tc_gemm, cudaFuncAttributeMaxDynamicSharedMemorySize, GEMM_SMEM);

    dim3 gemmGrid(4, (N + BM - 1) / BM);
    const int edgeBlocks = (E + 255) / 256;
    const int gatherBlocks = (N * 32 + 255) / 256;
    const int zeroNblocks = ((N / 4) + 255) / 256;

    auto splitW = [&](const float* B, __nv_bfloat16* th, __nv_bfloat16* tl, int K) {
        splitT_kernel<<<(K * 512 + 255) / 256, 256>>>(B, th, tl, K, 512);
    };
    auto gemm = [&](const float* A, const __nv_bfloat16* th, const __nv_bfloat16* tl,
                    const float* bias, const float* h, const float* g, float* C,
                    const float* dvec, float* dout, int K, int op) {
        tc_gemm<<<gemmGrid, 256, GEMM_SMEM>>>(A, th, tl, bias, h, g, C, dvec, dout, N, K, op);
    };
    auto zeroN = [&](float* p) { zero_kernel<<<zeroNblocks, 256>>>(p, N / 4); };

    // --- CSR build for both relations (edges are inputs; done once up front) ---
    zeroN((float*)cnt);
    hist_kernel<<<edgeBlocks, 256>>>(eIU1, cnt, E);
    scan_kernel<<<1, 512>>>(cnt, rowptr1, cursor, N);
    reorder_kernel<<<edgeBlocks, 256>>>(eIU1, eIU1 + E, cursor, csr1, E);
    zeroN((float*)cnt);
    hist_kernel<<<edgeBlocks, 256>>>(eUI0, cnt, E);
    scan_kernel<<<1, 512>>>(cnt, rowptr0, cursor, N);
    reorder_kernel<<<edgeBlocks, 256>>>(eUI0, eUI0 + E, cursor, csr0, E);

    // --- all 4 folded attention vectors in ONE full-chip launch ---
    prepw4_kernel<<<(4 * 513 * 32 + 255) / 256, 256>>>(gatW, gatb, aw, ws1, wt1, ws0, wt0);

    // --- node transforms with fused attention dots ---
    splitW(Wu, bth0, btl0, 512);                 // pair0 = Wu (reused at hop 0)
    splitW(Wi, bth1, btl1, 256);
    zeroN(ssc); zeroN(tsc);
    gemm(fu2, bth0, btl0, bu, nullptr, nullptr, bufA, wt1, tsc, 512, 0);  // su_h2 (+dot wt1)
    gemm(fi1, bth1, btl1, bi, nullptr, nullptr, bufB, ws1, ssc, 256, 0);  // hi_h1 (+dot ws1)

    // --- GAT rel 1 @ hop 1: head=hi_h1, tail=su_h2, edges_IU_h1 ---
    const float* fW1 = gatW + (size_t)H * H;
    const float* fb1 = gatb + H;
    gather_kernel<<<gatherBlocks, 256>>>(rowptr1, csr1, ssc, tsc,
                                         ws1 + 512, wt1 + 512, ab, 1, bufA, hp, N);
    splitW(fW1, bth1, btl1, 512);
    zeroN(ssc); zeroN(tsc);
    // si_new = (hi_h1 + (agg@fW1 + fb1) + gat_bias1) * 0.5  (+dot wt0 -> tsc for hop 0)
    gemm(hp, bth1, btl1, fb1, bufB, gbias + H, bufF, wt0, tsc, 512, 2);

    // --- GAT rel 0 @ hop 0: head=hu_h0, tail=si_new, edges_UI_h0 ---
    gemm(fu0, bth0, btl0, bu, nullptr, nullptr, bufG, ws0, ssc, 512, 0);  // hu_h0 (+dot ws0)
    gather_kernel<<<gatherBlocks, 256>>>(rowptr0, csr0, ssc, tsc,
                                         ws0 + 512, wt0 + 512, ab, 0, bufF, hp, N);
    splitW(gatW, bth1, btl1, 512);
    // su_final = (hu_h0 + (agg@fW0 + fb0) + gat_bias0) * 0.5
    gemm(hp, bth1, btl1, gatb, bufG, gbias, bufA, nullptr, nullptr, 512, 2);

    // --- Res_DNN head ---
    splitW(prepW, bth0, btl0, 512);
    gemm(bufA, bth0, btl0, prepb, nullptr, nullptr, bufB, nullptr, nullptr, 512, 0);  // x
    for (int r = 0; r < 2; r++) {
        splitW(dnnW + (size_t)(r * 2 + 0) * H * H, bth0, btl0, 512);
        gemm(bufB, bth0, btl0, dnnb + (r * 2 + 0) * H, nullptr, nullptr, bufC, nullptr, nullptr, 512, 1);
        ln_kernel<<<N, 128>>>(bufC, nullptr, lng + (r * 2 + 0) * H, lnb + (r * 2 + 0) * H,
                              nullptr, nullptr, nullptr, 0);
        splitW(dnnW + (size_t)(r * 2 + 1) * H * H, bth0, btl0, 512);
        gemm(bufC, bth0, btl0, dnnb + (r * 2 + 1) * H, nullptr, nullptr, bufD, nullptr, nullptr, 512, 1);
        ln_kernel<<<N, 128>>>(bufD, nullptr, lng + (r * 2 + 1) * H, lnb + (r * 2 + 1) * H,
                              nullptr, nullptr, nullptr, 0);
        // x = LN(tanh(sc + x)); last residual LN fuses classifier dot + sigmoid -> d_out
        if (r == 0) {
            ln_kernel<<<N, 128>>>(bufB, bufD, rlng + r * H, rlnb + r * H,
                                  nullptr, nullptr, nullptr, 1);
        } else {
            ln_kernel<<<N, 128>>>(bufB, bufD, rlng + r * H, rlnb + r * H,
                                  clsW, clsb, (float*)d_out, 1);
        }
    }
}